// round 2
// baseline (speedup 1.0000x reference)
#include <cuda_runtime.h>
#include <cuda_bf16.h>
#include <math.h>
#include <stdint.h>

#define B_ 4
#define S_ 1024
#define D_ 1024
#define H_ 16
#define M_ 4
#define R_ 64
#define DH_ 64
#define EPS_ 1e-8f

// ---------------- scratch (static device globals; no allocation) ----------------
__device__ __align__(16) float g_q[B_ * S_ * D_];
__device__ __align__(16) float g_k[B_ * S_ * D_];
__device__ __align__(16) float g_v[B_ * S_ * D_];
__device__ __align__(16) float g_lm[M_ * S_ * S_];
__device__ __align__(16) float g_gath[M_ * S_ * S_];
__device__ __align__(16) float g_ssq[B_ * H_];

// ---------------- helpers ----------------
__device__ __forceinline__ uint32_t f2tf(float x) {
    uint32_t u;
    asm("cvt.rna.tf32.f32 %0, %1;" : "=r"(u) : "f"(x));
    return u;
}
__device__ __forceinline__ float tfbits2f(uint32_t u) { return __uint_as_float(u); }

__device__ __forceinline__ void mma8(float d[4], const uint32_t a[4], const uint32_t b[2]) {
    asm volatile(
        "mma.sync.aligned.m16n8k8.row.col.f32.tf32.tf32.f32 "
        "{%0,%1,%2,%3},{%4,%5,%6,%7},{%8,%9},{%0,%1,%2,%3};"
        : "+f"(d[0]), "+f"(d[1]), "+f"(d[2]), "+f"(d[3])
        : "r"(a[0]), "r"(a[1]), "r"(a[2]), "r"(a[3]), "r"(b[0]), "r"(b[1]));
}

// ---------------- projection GEMM: Y[4096,1024] = X @ W^T + b (3xTF32) ----------------
// SEL: 0 -> g_q, 1 -> g_k, 2 -> g_v
// BM=128, BN=128, BK=32, 256 threads, warps 4(m) x 2(n), warp tile 32x64
template <int SEL>
__global__ __launch_bounds__(256) void proj_kernel(const float* __restrict__ X,
                                                   const float* __restrict__ W,
                                                   const float* __restrict__ bias) {
    float* __restrict__ Y = (SEL == 0) ? g_q : (SEL == 1) ? g_k : g_v;
    __shared__ float As[128][36];  // [m][k], pad 36 -> conflict-free frag loads
    __shared__ float Bs[128][36];  // [n][k]
    const int tid = threadIdx.x;
    const int warp = tid >> 5, lane = tid & 31;
    const int gid = lane >> 2, tig = lane & 3;
    const int wm = warp >> 1, wn = warp & 1;
    const int row0 = blockIdx.y * 128;
    const int col0 = blockIdx.x * 128;

    float acc[2][8][4];
#pragma unroll
    for (int mt = 0; mt < 2; mt++)
#pragma unroll
        for (int nt = 0; nt < 8; nt++)
#pragma unroll
            for (int r = 0; r < 4; r++) acc[mt][nt][r] = 0.f;

    for (int k0 = 0; k0 < D_; k0 += 32) {
#pragma unroll
        for (int it = 0; it < 4; it++) {
            int i = tid + it * 256;
            int r = i >> 3, c = (i & 7) << 2;
            *(float4*)&As[r][c] = *(const float4*)&X[(size_t)(row0 + r) * D_ + k0 + c];
            *(float4*)&Bs[r][c] = *(const float4*)&W[(size_t)(col0 + r) * D_ + k0 + c];
        }
        __syncthreads();
#pragma unroll
        for (int kc = 0; kc < 4; kc++) {
            uint32_t ah[2][4], al[2][4];
#pragma unroll
            for (int mt = 0; mt < 2; mt++) {
                int mrow = wm * 32 + mt * 16;
                float v0 = As[mrow + gid][kc * 8 + tig];
                float v1 = As[mrow + gid + 8][kc * 8 + tig];
                float v2 = As[mrow + gid][kc * 8 + tig + 4];
                float v3 = As[mrow + gid + 8][kc * 8 + tig + 4];
                ah[mt][0] = f2tf(v0); al[mt][0] = f2tf(v0 - tfbits2f(ah[mt][0]));
                ah[mt][1] = f2tf(v1); al[mt][1] = f2tf(v1 - tfbits2f(ah[mt][1]));
                ah[mt][2] = f2tf(v2); al[mt][2] = f2tf(v2 - tfbits2f(ah[mt][2]));
                ah[mt][3] = f2tf(v3); al[mt][3] = f2tf(v3 - tfbits2f(ah[mt][3]));
            }
#pragma unroll
            for (int nt = 0; nt < 8; nt++) {
                int nrow = wn * 64 + nt * 8 + gid;
                float w0 = Bs[nrow][kc * 8 + tig];
                float w1 = Bs[nrow][kc * 8 + tig + 4];
                uint32_t bh[2], bl[2];
                bh[0] = f2tf(w0); bl[0] = f2tf(w0 - tfbits2f(bh[0]));
                bh[1] = f2tf(w1); bl[1] = f2tf(w1 - tfbits2f(bh[1]));
#pragma unroll
                for (int mt = 0; mt < 2; mt++) {
                    mma8(acc[mt][nt], ah[mt], bh);
                    mma8(acc[mt][nt], al[mt], bh);
                    mma8(acc[mt][nt], ah[mt], bl);
                }
            }
        }
        __syncthreads();
    }
    // epilogue + bias
#pragma unroll
    for (int mt = 0; mt < 2; mt++) {
        int rg = row0 + wm * 32 + mt * 16 + gid;
#pragma unroll
        for (int nt = 0; nt < 8; nt++) {
            int cg = col0 + wn * 64 + nt * 8 + 2 * tig;
            float bx = bias[cg], by = bias[cg + 1];
            *(float2*)&Y[(size_t)rg * D_ + cg] =
                make_float2(acc[mt][nt][0] + bx, acc[mt][nt][1] + by);
            *(float2*)&Y[(size_t)(rg + 8) * D_ + cg] =
                make_float2(acc[mt][nt][2] + bx, acc[mt][nt][3] + by);
        }
    }
}

// ---------------- lm[m,s,t] = sum_r mask1[m,r,s] * mask2[m,r,t] (fp32) ----------------
__global__ __launch_bounds__(256) void lm_kernel(const float* __restrict__ m1,
                                                 const float* __restrict__ m2) {
    __shared__ float As[16][64];
    __shared__ float Bs[16][64];
    const int m = blockIdx.z;
    const int s0 = blockIdx.y * 64, t0 = blockIdx.x * 64;
    const int tid = threadIdx.x;
    const int tx = tid & 15, ty = tid >> 4;
    float acc[4][4];
#pragma unroll
    for (int i = 0; i < 4; i++)
#pragma unroll
        for (int j = 0; j < 4; j++) acc[i][j] = 0.f;

    for (int r0 = 0; r0 < R_; r0 += 16) {
        int rr = tid >> 4, cc = (tid & 15) << 2;
        *(float4*)&As[rr][cc] = *(const float4*)&m1[(size_t)((m * R_ + r0 + rr)) * S_ + s0 + cc];
        *(float4*)&Bs[rr][cc] = *(const float4*)&m2[(size_t)((m * R_ + r0 + rr)) * S_ + t0 + cc];
        __syncthreads();
#pragma unroll
        for (int r = 0; r < 16; r++) {
            float a[4], bb[4];
#pragma unroll
            for (int i = 0; i < 4; i++) a[i] = As[r][ty * 4 + i];
#pragma unroll
            for (int j = 0; j < 4; j++) bb[j] = Bs[r][tx + 16 * j];
#pragma unroll
            for (int i = 0; i < 4; i++)
#pragma unroll
                for (int j = 0; j < 4; j++) acc[i][j] += a[i] * bb[j];
        }
        __syncthreads();
    }
#pragma unroll
    for (int i = 0; i < 4; i++)
#pragma unroll
        for (int j = 0; j < 4; j++)
            g_lm[(size_t)(m * S_ + s0 + ty * 4 + i) * S_ + t0 + tx + 16 * j] = acc[i][j];
}

// ---------------- gathered[m,s,t] = lm[m,s,rb[m,s,t]]  (+ zero ssq) ----------------
// NOTE: roll_back is int32 on device (JAX canonicalizes int64 -> int32 without x64).
// Index is masked to [0, S) so a dtype surprise shows up as wrong output, not an IMA.
__global__ __launch_bounds__(256) void gather_kernel(const int* __restrict__ rb) {
    if (blockIdx.x == 0 && threadIdx.x < B_ * H_) g_ssq[threadIdx.x] = 0.f;
    int i4 = (blockIdx.x * 256 + threadIdx.x) * 4;  // over M*S*S
    int row = i4 >> 10;                             // combined (m*S + s)
    const float* lrow = &g_lm[(size_t)row << 10];
    int4 u = *(const int4*)&rb[i4];
    g_gath[i4 + 0] = lrow[u.x & (S_ - 1)];
    g_gath[i4 + 1] = lrow[u.y & (S_ - 1)];
    g_gath[i4 + 2] = lrow[u.z & (S_ - 1)];
    g_gath[i4 + 3] = lrow[u.w & (S_ - 1)];
}

// ---------------- fused attention ----------------
// grid (S/128, B*H), 256 thr (8 warps, warp tile m=16 over full n)
// smem: Ks[128][72], Vs[128][72], Ps(8 warps x [16][136], aliases Qs[128][72])
#define KS_OFF 0
#define VS_OFF 9216
#define PS_OFF 18432
#define ATT_SMEM_FLOATS (18432 + 8 * 16 * 136)
#define ATT_SMEM_BYTES (ATT_SMEM_FLOATS * 4)

__global__ __launch_bounds__(256) void attn_kernel(float* __restrict__ out) {
    extern __shared__ float sm[];
    float* Ks = sm + KS_OFF;
    float* Vs = sm + VS_OFF;
    float* Psa = sm + PS_OFF;
    float* Qs = Psa;  // alias: Q frags consumed before Ps written

    const int tid = threadIdx.x, warp = tid >> 5, lane = tid & 31;
    const int gid = lane >> 2, tig = lane & 3;
    const int bh = blockIdx.y;
    const int b = bh >> 4, h = bh & 15;
    const int midx = h & 3;
    const int s0 = blockIdx.x * 128;
    const int mrow = warp * 16;

    const float* Qg = g_q + (size_t)b * S_ * D_ + h * 64;
    const float* Kg = g_k + (size_t)b * S_ * D_ + h * 64;
    const float* Vg = g_v + (size_t)b * S_ * D_ + h * 64;
    const float* grow = g_gath + (size_t)midx * S_ * S_;

    // stage Q tile
#pragma unroll
    for (int it = 0; it < 8; it++) {
        int i = tid + it * 256;
        int r = i >> 4, c = (i & 15) << 2;
        *(float4*)&Qs[r * 72 + c] = *(const float4*)&Qg[(size_t)(s0 + r) * D_ + c];
    }
    __syncthreads();

    uint32_t qf[8][4];
#pragma unroll
    for (int kc = 0; kc < 8; kc++) {
        qf[kc][0] = f2tf(Qs[(mrow + gid) * 72 + kc * 8 + tig]);
        qf[kc][1] = f2tf(Qs[(mrow + gid + 8) * 72 + kc * 8 + tig]);
        qf[kc][2] = f2tf(Qs[(mrow + gid) * 72 + kc * 8 + tig + 4]);
        qf[kc][3] = f2tf(Qs[(mrow + gid + 8) * 72 + kc * 8 + tig + 4]);
    }
    __syncthreads();  // Qs free -> Ps may overwrite

    float oacc[8][4];
#pragma unroll
    for (int nt = 0; nt < 8; nt++)
#pragma unroll
        for (int r = 0; r < 4; r++) oacc[nt][r] = 0.f;
    float ssq = 0.f;
    float* Pw = Psa + warp * 16 * 136;

    for (int tt = 0; tt < 8; tt++) {
        const int t0 = tt * 128;
#pragma unroll
        for (int it = 0; it < 8; it++) {
            int i = tid + it * 256;
            int r = i >> 4, c = (i & 15) << 2;
            *(float4*)&Ks[r * 72 + c] = *(const float4*)&Kg[(size_t)(t0 + r) * D_ + c];
            *(float4*)&Vs[r * 72 + c] = *(const float4*)&Vg[(size_t)(t0 + r) * D_ + c];
        }
        __syncthreads();

        // P = Q K^T, then mask*scale, ssq, stash to Pw
#pragma unroll
        for (int nt = 0; nt < 16; nt++) {
            float p[4] = {0.f, 0.f, 0.f, 0.f};
#pragma unroll
            for (int kc = 0; kc < 8; kc++) {
                uint32_t bf[2];
                bf[0] = f2tf(Ks[(nt * 8 + gid) * 72 + kc * 8 + tig]);
                bf[1] = f2tf(Ks[(nt * 8 + gid) * 72 + kc * 8 + tig + 4]);
                mma8(p, qf[kc], bf);
            }
            int srow = s0 + mrow + gid;
            int tcol = t0 + nt * 8 + 2 * tig;
            float2 g0 = *(const float2*)&grow[(size_t)srow * S_ + tcol];
            float2 g1 = *(const float2*)&grow[(size_t)(srow + 8) * S_ + tcol];
            float v0 = p[0] * 0.125f * g0.x;
            float v1 = p[1] * 0.125f * g0.y;
            float v2 = p[2] * 0.125f * g1.x;
            float v3 = p[3] * 0.125f * g1.y;
            ssq += v0 * v0 + v1 * v1 + v2 * v2 + v3 * v3;
            *(float2*)&Pw[gid * 136 + nt * 8 + 2 * tig] = make_float2(v0, v1);
            *(float2*)&Pw[(gid + 8) * 136 + nt * 8 + 2 * tig] = make_float2(v2, v3);
        }
        __syncwarp();

        // O += P V
#pragma unroll
        for (int kc = 0; kc < 16; kc++) {
            uint32_t af[4];
            af[0] = f2tf(Pw[gid * 136 + kc * 8 + tig]);
            af[1] = f2tf(Pw[(gid + 8) * 136 + kc * 8 + tig]);
            af[2] = f2tf(Pw[gid * 136 + kc * 8 + tig + 4]);
            af[3] = f2tf(Pw[(gid + 8) * 136 + kc * 8 + tig + 4]);
#pragma unroll
            for (int nt = 0; nt < 8; nt++) {
                uint32_t bf[2];
                bf[0] = f2tf(Vs[(kc * 8 + tig) * 72 + nt * 8 + gid]);
                bf[1] = f2tf(Vs[(kc * 8 + tig + 4) * 72 + nt * 8 + gid]);
                mma8(oacc[nt], af, bf);
            }
        }
        __syncthreads();
    }

    // write unnormalized O
    float* Og = out + (size_t)b * S_ * D_ + h * 64;
#pragma unroll
    for (int nt = 0; nt < 8; nt++) {
        int srow = s0 + mrow + gid;
        int c = nt * 8 + 2 * tig;
        *(float2*)&Og[(size_t)srow * D_ + c] = make_float2(oacc[nt][0], oacc[nt][1]);
        *(float2*)&Og[(size_t)(srow + 8) * D_ + c] = make_float2(oacc[nt][2], oacc[nt][3]);
    }
    // ssq reduce + atomic
#pragma unroll
    for (int off = 16; off; off >>= 1) ssq += __shfl_xor_sync(0xffffffffu, ssq, off);
    if (lane == 0) atomicAdd(&g_ssq[bh], ssq);
}

// ---------------- final scale by 1/(||att||_F + eps) ----------------
__global__ __launch_bounds__(256) void scale_kernel(float* __restrict__ out) {
    int i4 = (blockIdx.x * 256 + threadIdx.x) * 4;  // over B*S*D
    int col = i4 & (D_ - 1);
    int h = col >> 6;
    int b = i4 >> 20;  // / (S_*D_)
    float f = 1.f / (sqrtf(g_ssq[b * H_ + h]) + EPS_);
    float4 v = *(float4*)&out[i4];
    v.x *= f; v.y *= f; v.z *= f; v.w *= f;
    *(float4*)&out[i4] = v;
}

// ---------------- launch ----------------
extern "C" void kernel_launch(void* const* d_in, const int* in_sizes, int n_in,
                              void* d_out, int out_size) {
    const float* x = (const float*)d_in[0];
    const float* Wk = (const float*)d_in[1];
    const float* bk = (const float*)d_in[2];
    const float* Wq = (const float*)d_in[3];
    const float* bq = (const float*)d_in[4];
    const float* Wv = (const float*)d_in[5];
    const float* bv = (const float*)d_in[6];
    const float* mask1 = (const float*)d_in[7];
    const float* mask2 = (const float*)d_in[8];
    const int* rb = (const int*)d_in[9];
    float* out = (float*)d_out;

    static bool attr_set = false;
    if (!attr_set) {
        cudaFuncSetAttribute(attn_kernel, cudaFuncAttributeMaxDynamicSharedMemorySize,
                             ATT_SMEM_BYTES);
        attr_set = true;
    }

    dim3 pgrid(D_ / 128, (B_ * S_) / 128);  // (8, 32)
    proj_kernel<0><<<pgrid, 256>>>(x, Wq, bq);
    proj_kernel<1><<<pgrid, 256>>>(x, Wk, bk);
    proj_kernel<2><<<pgrid, 256>>>(x, Wv, bv);

    lm_kernel<<<dim3(S_ / 64, S_ / 64, M_), 256>>>(mask1, mask2);
    gather_kernel<<<(M_ * S_ * S_) / 1024, 256>>>(rb);

    attn_kernel<<<dim3(S_ / 128, B_ * H_), 256, ATT_SMEM_BYTES>>>(out);

    scale_kernel<<<(B_ * S_ * D_) / 1024, 256>>>(out);
}

// round 3
// speedup vs baseline: 1.2167x; 1.2167x over previous
#include <cuda_runtime.h>
#include <cuda_bf16.h>
#include <math.h>
#include <stdint.h>

#define B_ 4
#define S_ 1024
#define D_ 1024
#define H_ 16
#define M_ 4
#define R_ 64
#define DH_ 64
#define EPS_ 1e-8f

// ---------------- scratch (static device globals; no allocation) ----------------
__device__ __align__(16) float g_q[B_ * S_ * D_];
__device__ __align__(16) float g_k[B_ * S_ * D_];
__device__ __align__(16) float g_v[B_ * S_ * D_];
__device__ __align__(16) float g_lm[M_ * S_ * S_];
__device__ __align__(16) float g_gath[M_ * S_ * S_];
__device__ __align__(16) float g_ssq[B_ * H_];

// ---------------- helpers ----------------
__device__ __forceinline__ uint32_t f2tf(float x) {
    uint32_t u;
    asm("cvt.rna.tf32.f32 %0, %1;" : "=r"(u) : "f"(x));
    return u;
}
__device__ __forceinline__ float tfbit(float x) { return __uint_as_float(f2tf(x)); }

__device__ __forceinline__ void mma8(float d[4], const uint32_t a[4], const uint32_t b[2]) {
    asm volatile(
        "mma.sync.aligned.m16n8k8.row.col.f32.tf32.tf32.f32 "
        "{%0,%1,%2,%3},{%4,%5,%6,%7},{%8,%9},{%0,%1,%2,%3};"
        : "+f"(d[0]), "+f"(d[1]), "+f"(d[2]), "+f"(d[3])
        : "r"(a[0]), "r"(a[1]), "r"(a[2]), "r"(a[3]), "r"(b[0]), "r"(b[1]));
}

__device__ __forceinline__ void mma16(float d[4], const uint32_t a[4], const uint32_t b[2]) {
    asm volatile(
        "mma.sync.aligned.m16n8k16.row.col.f32.bf16.bf16.f32 "
        "{%0,%1,%2,%3},{%4,%5,%6,%7},{%8,%9},{%0,%1,%2,%3};"
        : "+f"(d[0]), "+f"(d[1]), "+f"(d[2]), "+f"(d[3])
        : "r"(a[0]), "r"(a[1]), "r"(a[2]), "r"(a[3]), "r"(b[0]), "r"(b[1]));
}

__device__ __forceinline__ uint32_t bf2bits(__nv_bfloat162 h) {
    return *(uint32_t*)&h;
}

// ---------------- fused projection GEMM (bf16x3): Y = X @ W^T + b ----------------
// grid (8, 32, 3); z selects Q/K/V. BM=128, BN=128, BK=32, 256 threads,
// warps 4(m) x 2(n), warp tile 32x64. Split fp32 -> bf16 hi+lo at staging;
// 3 bf16 m16n8k16 passes (hh, lh, hl).
__global__ __launch_bounds__(256) void proj_kernel(const float* __restrict__ X,
                                                   const float* __restrict__ Wq,
                                                   const float* __restrict__ bq,
                                                   const float* __restrict__ Wk,
                                                   const float* __restrict__ bk,
                                                   const float* __restrict__ Wv,
                                                   const float* __restrict__ bv) {
    const float* W;
    const float* bias;
    float* Y;
    if (blockIdx.z == 0) { W = Wq; bias = bq; Y = g_q; }
    else if (blockIdx.z == 1) { W = Wk; bias = bk; Y = g_k; }
    else { W = Wv; bias = bv; Y = g_v; }

    // packed bf16x2 along k: 16 uint32 per row (K=32), stride 20 -> conflict-free
    __shared__ uint32_t Ah[128][20], Al[128][20], Bh[128][20], Bl[128][20];

    const int tid = threadIdx.x;
    const int warp = tid >> 5, lane = tid & 31;
    const int gid = lane >> 2, tig = lane & 3;
    const int wm = warp >> 1, wn = warp & 1;
    const int row0 = blockIdx.y * 128;
    const int col0 = blockIdx.x * 128;

    float acc[2][8][4];
#pragma unroll
    for (int mt = 0; mt < 2; mt++)
#pragma unroll
        for (int nt = 0; nt < 8; nt++)
#pragma unroll
            for (int r = 0; r < 4; r++) acc[mt][nt][r] = 0.f;

    for (int k0 = 0; k0 < D_; k0 += 32) {
#pragma unroll
        for (int it = 0; it < 4; it++) {
            int i = tid + it * 256;
            int r = i >> 3, c = (i & 7) << 2;  // c in {0..28}, float4 along k
            float4 xa = *(const float4*)&X[(size_t)(row0 + r) * D_ + k0 + c];
            float4 wa = *(const float4*)&W[(size_t)(col0 + r) * D_ + k0 + c];
            __nv_bfloat162 xh01 = __floats2bfloat162_rn(xa.x, xa.y);
            __nv_bfloat162 xh23 = __floats2bfloat162_rn(xa.z, xa.w);
            float2 xf01 = __bfloat1622float2(xh01);
            float2 xf23 = __bfloat1622float2(xh23);
            __nv_bfloat162 xl01 = __floats2bfloat162_rn(xa.x - xf01.x, xa.y - xf01.y);
            __nv_bfloat162 xl23 = __floats2bfloat162_rn(xa.z - xf23.x, xa.w - xf23.y);
            __nv_bfloat162 wh01 = __floats2bfloat162_rn(wa.x, wa.y);
            __nv_bfloat162 wh23 = __floats2bfloat162_rn(wa.z, wa.w);
            float2 wf01 = __bfloat1622float2(wh01);
            float2 wf23 = __bfloat1622float2(wh23);
            __nv_bfloat162 wl01 = __floats2bfloat162_rn(wa.x - wf01.x, wa.y - wf01.y);
            __nv_bfloat162 wl23 = __floats2bfloat162_rn(wa.z - wf23.x, wa.w - wf23.y);
            int cc = c >> 1;
            *(uint2*)&Ah[r][cc] = make_uint2(bf2bits(xh01), bf2bits(xh23));
            *(uint2*)&Al[r][cc] = make_uint2(bf2bits(xl01), bf2bits(xl23));
            *(uint2*)&Bh[r][cc] = make_uint2(bf2bits(wh01), bf2bits(wh23));
            *(uint2*)&Bl[r][cc] = make_uint2(bf2bits(wl01), bf2bits(wl23));
        }
        __syncthreads();
#pragma unroll
        for (int kc = 0; kc < 2; kc++) {  // two k16 chunks per BK=32
            uint32_t ah[2][4], al[2][4];
#pragma unroll
            for (int mt = 0; mt < 2; mt++) {
                int mrow = wm * 32 + mt * 16;
                ah[mt][0] = Ah[mrow + gid][kc * 8 + tig];
                ah[mt][1] = Ah[mrow + gid + 8][kc * 8 + tig];
                ah[mt][2] = Ah[mrow + gid][kc * 8 + tig + 4];
                ah[mt][3] = Ah[mrow + gid + 8][kc * 8 + tig + 4];
                al[mt][0] = Al[mrow + gid][kc * 8 + tig];
                al[mt][1] = Al[mrow + gid + 8][kc * 8 + tig];
                al[mt][2] = Al[mrow + gid][kc * 8 + tig + 4];
                al[mt][3] = Al[mrow + gid + 8][kc * 8 + tig + 4];
            }
#pragma unroll
            for (int nt = 0; nt < 8; nt++) {
                int nrow = wn * 64 + nt * 8 + gid;
                uint32_t bh[2], bl[2];
                bh[0] = Bh[nrow][kc * 8 + tig];
                bh[1] = Bh[nrow][kc * 8 + tig + 4];
                bl[0] = Bl[nrow][kc * 8 + tig];
                bl[1] = Bl[nrow][kc * 8 + tig + 4];
#pragma unroll
                for (int mt = 0; mt < 2; mt++) {
                    mma16(acc[mt][nt], ah[mt], bh);
                    mma16(acc[mt][nt], al[mt], bh);
                    mma16(acc[mt][nt], ah[mt], bl);
                }
            }
        }
        __syncthreads();
    }
    // epilogue + bias
#pragma unroll
    for (int mt = 0; mt < 2; mt++) {
        int rg = row0 + wm * 32 + mt * 16 + gid;
#pragma unroll
        for (int nt = 0; nt < 8; nt++) {
            int cg = col0 + wn * 64 + nt * 8 + 2 * tig;
            float bx = bias[cg], by = bias[cg + 1];
            *(float2*)&Y[(size_t)rg * D_ + cg] =
                make_float2(acc[mt][nt][0] + bx, acc[mt][nt][1] + by);
            *(float2*)&Y[(size_t)(rg + 8) * D_ + cg] =
                make_float2(acc[mt][nt][2] + bx, acc[mt][nt][3] + by);
        }
    }
}

// ---------------- lm[m,s,t] = sum_r mask1[m,r,s] * mask2[m,r,t] (fp32) ----------------
__global__ __launch_bounds__(256) void lm_kernel(const float* __restrict__ m1,
                                                 const float* __restrict__ m2) {
    __shared__ float As[16][64];
    __shared__ float Bs[16][64];
    const int m = blockIdx.z;
    const int s0 = blockIdx.y * 64, t0 = blockIdx.x * 64;
    const int tid = threadIdx.x;
    const int tx = tid & 15, ty = tid >> 4;
    float acc[4][4];
#pragma unroll
    for (int i = 0; i < 4; i++)
#pragma unroll
        for (int j = 0; j < 4; j++) acc[i][j] = 0.f;

    for (int r0 = 0; r0 < R_; r0 += 16) {
        int rr = tid >> 4, cc = (tid & 15) << 2;
        *(float4*)&As[rr][cc] = *(const float4*)&m1[(size_t)((m * R_ + r0 + rr)) * S_ + s0 + cc];
        *(float4*)&Bs[rr][cc] = *(const float4*)&m2[(size_t)((m * R_ + r0 + rr)) * S_ + t0 + cc];
        __syncthreads();
#pragma unroll
        for (int r = 0; r < 16; r++) {
            float a[4], bb[4];
#pragma unroll
            for (int i = 0; i < 4; i++) a[i] = As[r][ty * 4 + i];
#pragma unroll
            for (int j = 0; j < 4; j++) bb[j] = Bs[r][tx + 16 * j];
#pragma unroll
            for (int i = 0; i < 4; i++)
#pragma unroll
                for (int j = 0; j < 4; j++) acc[i][j] += a[i] * bb[j];
        }
        __syncthreads();
    }
#pragma unroll
    for (int i = 0; i < 4; i++)
#pragma unroll
        for (int j = 0; j < 4; j++)
            g_lm[(size_t)(m * S_ + s0 + ty * 4 + i) * S_ + t0 + tx + 16 * j] = acc[i][j];
}

// ---------------- gathered[m,s,t] = lm[m,s,rb[m,s,t]]  (+ zero ssq) ----------------
__global__ __launch_bounds__(256) void gather_kernel(const int* __restrict__ rb) {
    if (blockIdx.x == 0 && threadIdx.x < B_ * H_) g_ssq[threadIdx.x] = 0.f;
    int i4 = (blockIdx.x * 256 + threadIdx.x) * 4;  // over M*S*S
    int row = i4 >> 10;                             // combined (m*S + s)
    const float* lrow = &g_lm[(size_t)row << 10];
    int4 u = *(const int4*)&rb[i4];
    g_gath[i4 + 0] = lrow[u.x & (S_ - 1)];
    g_gath[i4 + 1] = lrow[u.y & (S_ - 1)];
    g_gath[i4 + 2] = lrow[u.z & (S_ - 1)];
    g_gath[i4 + 3] = lrow[u.w & (S_ - 1)];
}

// ---------------- fused attention ----------------
// grid (S/128, B*H), 256 thr (8 warps, warp tile m=16 over full n)
// K/V/Q/P pre-converted to tf32 bit patterns at staging (no cvts in MMA loops).
#define KS_OFF 0
#define VS_OFF 9216
#define PS_OFF 18432
#define ATT_SMEM_FLOATS (18432 + 8 * 16 * 136)
#define ATT_SMEM_BYTES (ATT_SMEM_FLOATS * 4)

__global__ __launch_bounds__(256) void attn_kernel(float* __restrict__ out) {
    extern __shared__ float sm[];
    float* Ks = sm + KS_OFF;
    float* Vs = sm + VS_OFF;
    float* Psa = sm + PS_OFF;
    float* Qs = Psa;  // alias: Q frags consumed before Ps written

    const int tid = threadIdx.x, warp = tid >> 5, lane = tid & 31;
    const int gid = lane >> 2, tig = lane & 3;
    const int bh = blockIdx.y;
    const int b = bh >> 4, h = bh & 15;
    const int midx = h & 3;
    const int s0 = blockIdx.x * 128;
    const int mrow = warp * 16;

    const float* Qg = g_q + (size_t)b * S_ * D_ + h * 64;
    const float* Kg = g_k + (size_t)b * S_ * D_ + h * 64;
    const float* Vg = g_v + (size_t)b * S_ * D_ + h * 64;
    const float* grow = g_gath + (size_t)midx * S_ * S_;

    // stage Q tile (pre-converted to tf32 bits)
#pragma unroll
    for (int it = 0; it < 8; it++) {
        int i = tid + it * 256;
        int r = i >> 4, c = (i & 15) << 2;
        float4 q4 = *(const float4*)&Qg[(size_t)(s0 + r) * D_ + c];
        *(float4*)&Qs[r * 72 + c] =
            make_float4(tfbit(q4.x), tfbit(q4.y), tfbit(q4.z), tfbit(q4.w));
    }
    __syncthreads();

    uint32_t qf[8][4];
#pragma unroll
    for (int kc = 0; kc < 8; kc++) {
        qf[kc][0] = __float_as_uint(Qs[(mrow + gid) * 72 + kc * 8 + tig]);
        qf[kc][1] = __float_as_uint(Qs[(mrow + gid + 8) * 72 + kc * 8 + tig]);
        qf[kc][2] = __float_as_uint(Qs[(mrow + gid) * 72 + kc * 8 + tig + 4]);
        qf[kc][3] = __float_as_uint(Qs[(mrow + gid + 8) * 72 + kc * 8 + tig + 4]);
    }
    __syncthreads();  // Qs free -> Ps may overwrite

    float oacc[8][4];
#pragma unroll
    for (int nt = 0; nt < 8; nt++)
#pragma unroll
        for (int r = 0; r < 4; r++) oacc[nt][r] = 0.f;
    float ssq = 0.f;
    float* Pw = Psa + warp * 16 * 136;

    for (int tt = 0; tt < 8; tt++) {
        const int t0 = tt * 128;
#pragma unroll
        for (int it = 0; it < 8; it++) {
            int i = tid + it * 256;
            int r = i >> 4, c = (i & 15) << 2;
            float4 k4 = *(const float4*)&Kg[(size_t)(t0 + r) * D_ + c];
            float4 v4 = *(const float4*)&Vg[(size_t)(t0 + r) * D_ + c];
            *(float4*)&Ks[r * 72 + c] =
                make_float4(tfbit(k4.x), tfbit(k4.y), tfbit(k4.z), tfbit(k4.w));
            *(float4*)&Vs[r * 72 + c] =
                make_float4(tfbit(v4.x), tfbit(v4.y), tfbit(v4.z), tfbit(v4.w));
        }
        __syncthreads();

        // P = Q K^T, then mask*scale, ssq, stash to Pw (tf32 bits)
#pragma unroll
        for (int nt = 0; nt < 16; nt++) {
            float p[4] = {0.f, 0.f, 0.f, 0.f};
#pragma unroll
            for (int kc = 0; kc < 8; kc++) {
                uint32_t bf[2];
                bf[0] = __float_as_uint(Ks[(nt * 8 + gid) * 72 + kc * 8 + tig]);
                bf[1] = __float_as_uint(Ks[(nt * 8 + gid) * 72 + kc * 8 + tig + 4]);
                mma8(p, qf[kc], bf);
            }
            int srow = s0 + mrow + gid;
            int tcol = t0 + nt * 8 + 2 * tig;
            float2 g0 = *(const float2*)&grow[(size_t)srow * S_ + tcol];
            float2 g1 = *(const float2*)&grow[(size_t)(srow + 8) * S_ + tcol];
            float v0 = p[0] * 0.125f * g0.x;
            float v1 = p[1] * 0.125f * g0.y;
            float v2 = p[2] * 0.125f * g1.x;
            float v3 = p[3] * 0.125f * g1.y;
            ssq += v0 * v0 + v1 * v1 + v2 * v2 + v3 * v3;
            *(float2*)&Pw[gid * 136 + nt * 8 + 2 * tig] =
                make_float2(tfbit(v0), tfbit(v1));
            *(float2*)&Pw[(gid + 8) * 136 + nt * 8 + 2 * tig] =
                make_float2(tfbit(v2), tfbit(v3));
        }
        __syncwarp();

        // O += P V
#pragma unroll
        for (int kc = 0; kc < 16; kc++) {
            uint32_t af[4];
            af[0] = __float_as_uint(Pw[gid * 136 + kc * 8 + tig]);
            af[1] = __float_as_uint(Pw[(gid + 8) * 136 + kc * 8 + tig]);
            af[2] = __float_as_uint(Pw[gid * 136 + kc * 8 + tig + 4]);
            af[3] = __float_as_uint(Pw[(gid + 8) * 136 + kc * 8 + tig + 4]);
#pragma unroll
            for (int nt = 0; nt < 8; nt++) {
                uint32_t bf[2];
                bf[0] = __float_as_uint(Vs[(kc * 8 + tig) * 72 + nt * 8 + gid]);
                bf[1] = __float_as_uint(Vs[(kc * 8 + tig + 4) * 72 + nt * 8 + gid]);
                mma8(oacc[nt], af, bf);
            }
        }
        __syncthreads();
    }

    // write unnormalized O
    float* Og = out + (size_t)b * S_ * D_ + h * 64;
#pragma unroll
    for (int nt = 0; nt < 8; nt++) {
        int srow = s0 + mrow + gid;
        int c = nt * 8 + 2 * tig;
        *(float2*)&Og[(size_t)srow * D_ + c] = make_float2(oacc[nt][0], oacc[nt][1]);
        *(float2*)&Og[(size_t)(srow + 8) * D_ + c] = make_float2(oacc[nt][2], oacc[nt][3]);
    }
    // ssq reduce + atomic
#pragma unroll
    for (int off = 16; off; off >>= 1) ssq += __shfl_xor_sync(0xffffffffu, ssq, off);
    if (lane == 0) atomicAdd(&g_ssq[bh], ssq);
}

// ---------------- final scale by 1/(||att||_F + eps) ----------------
__global__ __launch_bounds__(256) void scale_kernel(float* __restrict__ out) {
    int i4 = (blockIdx.x * 256 + threadIdx.x) * 4;  // over B*S*D
    int col = i4 & (D_ - 1);
    int h = col >> 6;
    int b = i4 >> 20;  // / (S_*D_)
    float f = 1.f / (sqrtf(g_ssq[b * H_ + h]) + EPS_);
    float4 v = *(float4*)&out[i4];
    v.x *= f; v.y *= f; v.z *= f; v.w *= f;
    *(float4*)&out[i4] = v;
}

// ---------------- launch ----------------
extern "C" void kernel_launch(void* const* d_in, const int* in_sizes, int n_in,
                              void* d_out, int out_size) {
    const float* x = (const float*)d_in[0];
    const float* Wk = (const float*)d_in[1];
    const float* bk = (const float*)d_in[2];
    const float* Wq = (const float*)d_in[3];
    const float* bq = (const float*)d_in[4];
    const float* Wv = (const float*)d_in[5];
    const float* bv = (const float*)d_in[6];
    const float* mask1 = (const float*)d_in[7];
    const float* mask2 = (const float*)d_in[8];
    const int* rb = (const int*)d_in[9];
    float* out = (float*)d_out;

    static bool attr_set = false;
    if (!attr_set) {
        cudaFuncSetAttribute(attn_kernel, cudaFuncAttributeMaxDynamicSharedMemorySize,
                             ATT_SMEM_BYTES);
        attr_set = true;
    }

    dim3 pgrid(D_ / 128, (B_ * S_) / 128, 3);  // (8, 32, 3)
    proj_kernel<<<pgrid, 256>>>(x, Wq, bq, Wk, bk, Wv, bv);

    lm_kernel<<<dim3(S_ / 64, S_ / 64, M_), 256>>>(mask1, mask2);
    gather_kernel<<<(M_ * S_ * S_) / 1024, 256>>>(rb);

    attn_kernel<<<dim3(S_ / 128, B_ * H_), 256, ATT_SMEM_BYTES>>>(out);

    scale_kernel<<<(B_ * S_ * D_) / 1024, 256>>>(out);
}

// round 4
// speedup vs baseline: 1.7488x; 1.4374x over previous
#include <cuda_runtime.h>
#include <cuda_bf16.h>
#include <math.h>
#include <stdint.h>

#define B_ 4
#define S_ 1024
#define D_ 1024
#define H_ 16
#define M_ 4
#define R_ 64
#define DH_ 64
#define EPS_ 1e-8f

// ---------------- scratch (static device globals; no allocation) ----------------
__device__ __align__(16) float g_q[B_ * S_ * D_];
__device__ __align__(16) float g_k[B_ * S_ * D_];
__device__ __align__(16) float g_v[B_ * S_ * D_];
__device__ __align__(16) float g_lm[M_ * S_ * S_];
__device__ __align__(16) float g_gath[M_ * S_ * S_];
__device__ __align__(16) float g_ssq[B_ * H_];

// ---------------- helpers ----------------
__device__ __forceinline__ uint32_t f2tf(float x) {
    uint32_t u;
    asm("cvt.rna.tf32.f32 %0, %1;" : "=r"(u) : "f"(x));
    return u;
}
__device__ __forceinline__ float tfbit(float x) { return __uint_as_float(f2tf(x)); }

__device__ __forceinline__ void mma8(float d[4], const uint32_t a[4], const uint32_t b[2]) {
    asm volatile(
        "mma.sync.aligned.m16n8k8.row.col.f32.tf32.tf32.f32 "
        "{%0,%1,%2,%3},{%4,%5,%6,%7},{%8,%9},{%0,%1,%2,%3};"
        : "+f"(d[0]), "+f"(d[1]), "+f"(d[2]), "+f"(d[3])
        : "r"(a[0]), "r"(a[1]), "r"(a[2]), "r"(a[3]), "r"(b[0]), "r"(b[1]));
}

__device__ __forceinline__ void mma16(float d[4], const uint32_t a[4], const uint32_t b[2]) {
    asm volatile(
        "mma.sync.aligned.m16n8k16.row.col.f32.bf16.bf16.f32 "
        "{%0,%1,%2,%3},{%4,%5,%6,%7},{%8,%9},{%0,%1,%2,%3};"
        : "+f"(d[0]), "+f"(d[1]), "+f"(d[2]), "+f"(d[3])
        : "r"(a[0]), "r"(a[1]), "r"(a[2]), "r"(a[3]), "r"(b[0]), "r"(b[1]));
}

__device__ __forceinline__ uint32_t bf2bits(__nv_bfloat162 h) {
    return *(uint32_t*)&h;
}

// ---------------- fused projection GEMM (bf16x3): Y = X @ W^T + b ----------------
// grid (8, 32, 3); z selects Q/K/V. BM=128, BN=128, BK=32, 256 threads,
// warps 4(m) x 2(n), warp tile 32x64. Split fp32 -> bf16 hi+lo at staging;
// 3 bf16 m16n8k16 passes (hh, lh, hl).
__global__ __launch_bounds__(256) void proj_kernel(const float* __restrict__ X,
                                                   const float* __restrict__ Wq,
                                                   const float* __restrict__ bq,
                                                   const float* __restrict__ Wk,
                                                   const float* __restrict__ bk,
                                                   const float* __restrict__ Wv,
                                                   const float* __restrict__ bv) {
    const float* W;
    const float* bias;
    float* Y;
    if (blockIdx.z == 0) { W = Wq; bias = bq; Y = g_q; }
    else if (blockIdx.z == 1) { W = Wk; bias = bk; Y = g_k; }
    else { W = Wv; bias = bv; Y = g_v; }

    __shared__ uint32_t Ah[128][20], Al[128][20], Bh[128][20], Bl[128][20];

    const int tid = threadIdx.x;
    const int warp = tid >> 5, lane = tid & 31;
    const int gid = lane >> 2, tig = lane & 3;
    const int wm = warp >> 1, wn = warp & 1;
    const int row0 = blockIdx.y * 128;
    const int col0 = blockIdx.x * 128;

    float acc[2][8][4];
#pragma unroll
    for (int mt = 0; mt < 2; mt++)
#pragma unroll
        for (int nt = 0; nt < 8; nt++)
#pragma unroll
            for (int r = 0; r < 4; r++) acc[mt][nt][r] = 0.f;

    for (int k0 = 0; k0 < D_; k0 += 32) {
#pragma unroll
        for (int it = 0; it < 4; it++) {
            int i = tid + it * 256;
            int r = i >> 3, c = (i & 7) << 2;
            float4 xa = *(const float4*)&X[(size_t)(row0 + r) * D_ + k0 + c];
            float4 wa = *(const float4*)&W[(size_t)(col0 + r) * D_ + k0 + c];
            __nv_bfloat162 xh01 = __floats2bfloat162_rn(xa.x, xa.y);
            __nv_bfloat162 xh23 = __floats2bfloat162_rn(xa.z, xa.w);
            float2 xf01 = __bfloat1622float2(xh01);
            float2 xf23 = __bfloat1622float2(xh23);
            __nv_bfloat162 xl01 = __floats2bfloat162_rn(xa.x - xf01.x, xa.y - xf01.y);
            __nv_bfloat162 xl23 = __floats2bfloat162_rn(xa.z - xf23.x, xa.w - xf23.y);
            __nv_bfloat162 wh01 = __floats2bfloat162_rn(wa.x, wa.y);
            __nv_bfloat162 wh23 = __floats2bfloat162_rn(wa.z, wa.w);
            float2 wf01 = __bfloat1622float2(wh01);
            float2 wf23 = __bfloat1622float2(wh23);
            __nv_bfloat162 wl01 = __floats2bfloat162_rn(wa.x - wf01.x, wa.y - wf01.y);
            __nv_bfloat162 wl23 = __floats2bfloat162_rn(wa.z - wf23.x, wa.w - wf23.y);
            int cc = c >> 1;
            *(uint2*)&Ah[r][cc] = make_uint2(bf2bits(xh01), bf2bits(xh23));
            *(uint2*)&Al[r][cc] = make_uint2(bf2bits(xl01), bf2bits(xl23));
            *(uint2*)&Bh[r][cc] = make_uint2(bf2bits(wh01), bf2bits(wh23));
            *(uint2*)&Bl[r][cc] = make_uint2(bf2bits(wl01), bf2bits(wl23));
        }
        __syncthreads();
#pragma unroll
        for (int kc = 0; kc < 2; kc++) {
            uint32_t ah[2][4], al[2][4];
#pragma unroll
            for (int mt = 0; mt < 2; mt++) {
                int mrow = wm * 32 + mt * 16;
                ah[mt][0] = Ah[mrow + gid][kc * 8 + tig];
                ah[mt][1] = Ah[mrow + gid + 8][kc * 8 + tig];
                ah[mt][2] = Ah[mrow + gid][kc * 8 + tig + 4];
                ah[mt][3] = Ah[mrow + gid + 8][kc * 8 + tig + 4];
                al[mt][0] = Al[mrow + gid][kc * 8 + tig];
                al[mt][1] = Al[mrow + gid + 8][kc * 8 + tig];
                al[mt][2] = Al[mrow + gid][kc * 8 + tig + 4];
                al[mt][3] = Al[mrow + gid + 8][kc * 8 + tig + 4];
            }
#pragma unroll
            for (int nt = 0; nt < 8; nt++) {
                int nrow = wn * 64 + nt * 8 + gid;
                uint32_t bh[2], bl[2];
                bh[0] = Bh[nrow][kc * 8 + tig];
                bh[1] = Bh[nrow][kc * 8 + tig + 4];
                bl[0] = Bl[nrow][kc * 8 + tig];
                bl[1] = Bl[nrow][kc * 8 + tig + 4];
#pragma unroll
                for (int mt = 0; mt < 2; mt++) {
                    mma16(acc[mt][nt], ah[mt], bh);
                    mma16(acc[mt][nt], al[mt], bh);
                    mma16(acc[mt][nt], ah[mt], bl);
                }
            }
        }
        __syncthreads();
    }
#pragma unroll
    for (int mt = 0; mt < 2; mt++) {
        int rg = row0 + wm * 32 + mt * 16 + gid;
#pragma unroll
        for (int nt = 0; nt < 8; nt++) {
            int cg = col0 + wn * 64 + nt * 8 + 2 * tig;
            float bx = bias[cg], by = bias[cg + 1];
            *(float2*)&Y[(size_t)rg * D_ + cg] =
                make_float2(acc[mt][nt][0] + bx, acc[mt][nt][1] + by);
            *(float2*)&Y[(size_t)(rg + 8) * D_ + cg] =
                make_float2(acc[mt][nt][2] + bx, acc[mt][nt][3] + by);
        }
    }
}

// ---------------- lm[m,s,t] = sum_r mask1[m,r,s] * mask2[m,r,t] (fp32) ----------------
__global__ __launch_bounds__(256) void lm_kernel(const float* __restrict__ m1,
                                                 const float* __restrict__ m2) {
    __shared__ float As[16][64];
    __shared__ float Bs[16][64];
    const int m = blockIdx.z;
    const int s0 = blockIdx.y * 64, t0 = blockIdx.x * 64;
    const int tid = threadIdx.x;
    const int tx = tid & 15, ty = tid >> 4;
    float acc[4][4];
#pragma unroll
    for (int i = 0; i < 4; i++)
#pragma unroll
        for (int j = 0; j < 4; j++) acc[i][j] = 0.f;

    for (int r0 = 0; r0 < R_; r0 += 16) {
        int rr = tid >> 4, cc = (tid & 15) << 2;
        *(float4*)&As[rr][cc] = *(const float4*)&m1[(size_t)((m * R_ + r0 + rr)) * S_ + s0 + cc];
        *(float4*)&Bs[rr][cc] = *(const float4*)&m2[(size_t)((m * R_ + r0 + rr)) * S_ + t0 + cc];
        __syncthreads();
#pragma unroll
        for (int r = 0; r < 16; r++) {
            float a[4], bb[4];
#pragma unroll
            for (int i = 0; i < 4; i++) a[i] = As[r][ty * 4 + i];
#pragma unroll
            for (int j = 0; j < 4; j++) bb[j] = Bs[r][tx + 16 * j];
#pragma unroll
            for (int i = 0; i < 4; i++)
#pragma unroll
                for (int j = 0; j < 4; j++) acc[i][j] += a[i] * bb[j];
        }
        __syncthreads();
    }
#pragma unroll
    for (int i = 0; i < 4; i++)
#pragma unroll
        for (int j = 0; j < 4; j++)
            g_lm[(size_t)(m * S_ + s0 + ty * 4 + i) * S_ + t0 + tx + 16 * j] = acc[i][j];
}

// ---------------- gathered[m,s,t] = lm[m,s,rb[m,s,t]]  (+ zero ssq) ----------------
__global__ __launch_bounds__(256) void gather_kernel(const int* __restrict__ rb) {
    if (blockIdx.x == 0 && threadIdx.x < B_ * H_) g_ssq[threadIdx.x] = 0.f;
    int i4 = (blockIdx.x * 256 + threadIdx.x) * 4;  // over M*S*S
    int row = i4 >> 10;                             // combined (m*S + s)
    const float* lrow = &g_lm[(size_t)row << 10];
    int4 u = *(const int4*)&rb[i4];
    g_gath[i4 + 0] = lrow[u.x & (S_ - 1)];
    g_gath[i4 + 1] = lrow[u.y & (S_ - 1)];
    g_gath[i4 + 2] = lrow[u.z & (S_ - 1)];
    g_gath[i4 + 3] = lrow[u.w & (S_ - 1)];
}

// ---------------- fused attention (shuffle P re-fragmentation, no P smem) ----------------
// grid (S/128, B*H), 256 thr (8 warps, warp tile m=16 over full n).
// smem: Ks[128][76] (K, also Q staging), Vs[128][72]. 2 CTAs/SM.
#define KSTRIDE 76
#define VSTRIDE 72
#define ATT_SMEM_FLOATS (128 * KSTRIDE + 128 * VSTRIDE)
#define ATT_SMEM_BYTES (ATT_SMEM_FLOATS * 4)

__global__ __launch_bounds__(256, 2) void attn_kernel(float* __restrict__ out) {
    extern __shared__ float sm[];
    float* Ks = sm;                   // 128 x 76 (K tile; Q staged here first)
    float* Vs = sm + 128 * KSTRIDE;   // 128 x 72

    const int tid = threadIdx.x, warp = tid >> 5, lane = tid & 31;
    const int gid = lane >> 2, tig = lane & 3;
    const int bh = blockIdx.y;
    const int b = bh >> 4, h = bh & 15;
    const int midx = h & 3;
    const int s0 = blockIdx.x * 128;
    const int mrow = warp * 16;

    const float* Qg = g_q + (size_t)b * S_ * D_ + h * 64;
    const float* Kg = g_k + (size_t)b * S_ * D_ + h * 64;
    const float* Vg = g_v + (size_t)b * S_ * D_ + h * 64;
    const float* grow = g_gath + (size_t)midx * S_ * S_;

    // stage Q tile into Ks (pre-converted to tf32 bits), extract frags
#pragma unroll
    for (int it = 0; it < 8; it++) {
        int i = tid + it * 256;
        int r = i >> 4, c = (i & 15) << 2;
        float4 q4 = *(const float4*)&Qg[(size_t)(s0 + r) * D_ + c];
        *(float4*)&Ks[r * KSTRIDE + c] =
            make_float4(tfbit(q4.x), tfbit(q4.y), tfbit(q4.z), tfbit(q4.w));
    }
    __syncthreads();

    uint32_t qf[8][4];
#pragma unroll
    for (int kc = 0; kc < 8; kc++) {
        qf[kc][0] = __float_as_uint(Ks[(mrow + gid) * KSTRIDE + kc * 8 + tig]);
        qf[kc][1] = __float_as_uint(Ks[(mrow + gid + 8) * KSTRIDE + kc * 8 + tig]);
        qf[kc][2] = __float_as_uint(Ks[(mrow + gid) * KSTRIDE + kc * 8 + tig + 4]);
        qf[kc][3] = __float_as_uint(Ks[(mrow + gid + 8) * KSTRIDE + kc * 8 + tig + 4]);
    }
    __syncthreads();  // Q frags in regs; Ks free for K tiles

    float oacc[8][4];
#pragma unroll
    for (int nt = 0; nt < 8; nt++)
#pragma unroll
        for (int r = 0; r < 4; r++) oacc[nt][r] = 0.f;
    float ssq = 0.f;

    const int srcA = (lane & ~3) | (tig >> 1);  // shfl source for cols t (a0,a1)
    const int srcB = srcA + 2;                  // shfl source for cols t+4 (a2,a3)
    const bool odd = (tig & 1);

    for (int tt = 0; tt < 8; tt++) {
        const int t0 = tt * 128;
#pragma unroll
        for (int it = 0; it < 8; it++) {
            int i = tid + it * 256;
            int r = i >> 4, c = (i & 15) << 2;
            float4 k4 = *(const float4*)&Kg[(size_t)(t0 + r) * D_ + c];
            float4 v4 = *(const float4*)&Vg[(size_t)(t0 + r) * D_ + c];
            *(float4*)&Ks[r * KSTRIDE + c] =
                make_float4(tfbit(k4.x), tfbit(k4.y), tfbit(k4.z), tfbit(k4.w));
            *(float4*)&Vs[r * VSTRIDE + c] =
                make_float4(tfbit(v4.x), tfbit(v4.y), tfbit(v4.z), tfbit(v4.w));
        }
        __syncthreads();

#pragma unroll
        for (int nt = 0; nt < 16; nt++) {
            // P tile (16 x 8) = Q K^T
            float p[4] = {0.f, 0.f, 0.f, 0.f};
#pragma unroll
            for (int kc = 0; kc < 8; kc++) {
                uint32_t bf[2];
                bf[0] = __float_as_uint(Ks[(nt * 8 + gid) * KSTRIDE + kc * 8 + tig]);
                bf[1] = __float_as_uint(Ks[(nt * 8 + gid) * KSTRIDE + kc * 8 + tig + 4]);
                mma8(p, qf[kc], bf);
            }
            // mask * scale + ssq
            int srow = s0 + mrow + gid;
            int tcol = t0 + nt * 8 + 2 * tig;
            float2 g0 = *(const float2*)&grow[(size_t)srow * S_ + tcol];
            float2 g1 = *(const float2*)&grow[(size_t)(srow + 8) * S_ + tcol];
            float v0 = p[0] * 0.125f * g0.x;
            float v1 = p[1] * 0.125f * g0.y;
            float v2 = p[2] * 0.125f * g1.x;
            float v3 = p[3] * 0.125f * g1.y;
            ssq += v0 * v0 + v1 * v1 + v2 * v2 + v3 * v3;
            // tf32-convert then C-frag -> A-frag cross-lane permutation
            float c0 = tfbit(v0), c1 = tfbit(v1), c2 = tfbit(v2), c3 = tfbit(v3);
            float w00 = __shfl_sync(0xffffffffu, c0, srcA);
            float w01 = __shfl_sync(0xffffffffu, c1, srcA);
            float w10 = __shfl_sync(0xffffffffu, c2, srcA);
            float w11 = __shfl_sync(0xffffffffu, c3, srcA);
            float w20 = __shfl_sync(0xffffffffu, c0, srcB);
            float w21 = __shfl_sync(0xffffffffu, c1, srcB);
            float w30 = __shfl_sync(0xffffffffu, c2, srcB);
            float w31 = __shfl_sync(0xffffffffu, c3, srcB);
            uint32_t af[4];
            af[0] = __float_as_uint(odd ? w01 : w00);
            af[1] = __float_as_uint(odd ? w11 : w10);
            af[2] = __float_as_uint(odd ? w21 : w20);
            af[3] = __float_as_uint(odd ? w31 : w30);
            // O += P_chunk * V_chunk  (k-chunk = nt)
#pragma unroll
            for (int vn = 0; vn < 8; vn++) {
                uint32_t bf[2];
                bf[0] = __float_as_uint(Vs[(nt * 8 + tig) * VSTRIDE + vn * 8 + gid]);
                bf[1] = __float_as_uint(Vs[(nt * 8 + tig + 4) * VSTRIDE + vn * 8 + gid]);
                mma8(oacc[vn], af, bf);
            }
        }
        __syncthreads();
    }

    // write unnormalized O
    float* Og = out + (size_t)b * S_ * D_ + h * 64;
#pragma unroll
    for (int nt = 0; nt < 8; nt++) {
        int srow = s0 + mrow + gid;
        int c = nt * 8 + 2 * tig;
        *(float2*)&Og[(size_t)srow * D_ + c] = make_float2(oacc[nt][0], oacc[nt][1]);
        *(float2*)&Og[(size_t)(srow + 8) * D_ + c] = make_float2(oacc[nt][2], oacc[nt][3]);
    }
    // ssq reduce + atomic
#pragma unroll
    for (int off = 16; off; off >>= 1) ssq += __shfl_xor_sync(0xffffffffu, ssq, off);
    if (lane == 0) atomicAdd(&g_ssq[bh], ssq);
}

// ---------------- final scale by 1/(||att||_F + eps) ----------------
__global__ __launch_bounds__(256) void scale_kernel(float* __restrict__ out) {
    int i4 = (blockIdx.x * 256 + threadIdx.x) * 4;  // over B*S*D
    int col = i4 & (D_ - 1);
    int h = col >> 6;
    int b = i4 >> 20;  // / (S_*D_)
    float f = 1.f / (sqrtf(g_ssq[b * H_ + h]) + EPS_);
    float4 v = *(float4*)&out[i4];
    v.x *= f; v.y *= f; v.z *= f; v.w *= f;
    *(float4*)&out[i4] = v;
}

// ---------------- launch ----------------
extern "C" void kernel_launch(void* const* d_in, const int* in_sizes, int n_in,
                              void* d_out, int out_size) {
    const float* x = (const float*)d_in[0];
    const float* Wk = (const float*)d_in[1];
    const float* bk = (const float*)d_in[2];
    const float* Wq = (const float*)d_in[3];
    const float* bq = (const float*)d_in[4];
    const float* Wv = (const float*)d_in[5];
    const float* bv = (const float*)d_in[6];
    const float* mask1 = (const float*)d_in[7];
    const float* mask2 = (const float*)d_in[8];
    const int* rb = (const int*)d_in[9];
    float* out = (float*)d_out;

    static bool attr_set = false;
    if (!attr_set) {
        cudaFuncSetAttribute(attn_kernel, cudaFuncAttributeMaxDynamicSharedMemorySize,
                             ATT_SMEM_BYTES);
        attr_set = true;
    }

    dim3 pgrid(D_ / 128, (B_ * S_) / 128, 3);  // (8, 32, 3)
    proj_kernel<<<pgrid, 256>>>(x, Wq, bq, Wk, bk, Wv, bv);

    lm_kernel<<<dim3(S_ / 64, S_ / 64, M_), 256>>>(mask1, mask2);
    gather_kernel<<<(M_ * S_ * S_) / 1024, 256>>>(rb);

    attn_kernel<<<dim3(S_ / 128, B_ * H_), 256, ATT_SMEM_BYTES>>>(out);

    scale_kernel<<<(B_ * S_ * D_) / 1024, 256>>>(out);
}

// round 5
// speedup vs baseline: 1.9425x; 1.1107x over previous
#include <cuda_runtime.h>
#include <cuda_bf16.h>
#include <math.h>
#include <stdint.h>

#define B_ 4
#define S_ 1024
#define D_ 1024
#define H_ 16
#define M_ 4
#define R_ 64
#define DH_ 64
#define EPS_ 1e-8f

// ---------------- scratch (static device globals; no allocation) ----------------
__device__ __align__(16) float g_q[B_ * S_ * D_];
__device__ __align__(16) float g_k[B_ * S_ * D_];
__device__ __align__(16) float g_v[B_ * S_ * D_];
__device__ __align__(16) float g_lm[M_ * S_ * S_];
__device__ __align__(16) float g_gath[M_ * S_ * S_];
__device__ __align__(16) float g_ssq[B_ * H_];
// packed bf16x2 (hi/lo split) staging of X and W: [row][k/2]
__device__ __align__(16) uint32_t g_xh[B_ * S_ * (D_ / 2)];
__device__ __align__(16) uint32_t g_xl[B_ * S_ * (D_ / 2)];
__device__ __align__(16) uint32_t g_wh[3 * D_ * (D_ / 2)];
__device__ __align__(16) uint32_t g_wl[3 * D_ * (D_ / 2)];

// ---------------- helpers ----------------
__device__ __forceinline__ uint32_t f2tf(float x) {
    uint32_t u;
    asm("cvt.rna.tf32.f32 %0, %1;" : "=r"(u) : "f"(x));
    return u;
}
__device__ __forceinline__ float tfbit(float x) { return __uint_as_float(f2tf(x)); }

__device__ __forceinline__ void mma8(float d[4], const uint32_t a[4], const uint32_t b[2]) {
    asm volatile(
        "mma.sync.aligned.m16n8k8.row.col.f32.tf32.tf32.f32 "
        "{%0,%1,%2,%3},{%4,%5,%6,%7},{%8,%9},{%0,%1,%2,%3};"
        : "+f"(d[0]), "+f"(d[1]), "+f"(d[2]), "+f"(d[3])
        : "r"(a[0]), "r"(a[1]), "r"(a[2]), "r"(a[3]), "r"(b[0]), "r"(b[1]));
}

__device__ __forceinline__ void mma16(float d[4], const uint32_t a[4], const uint32_t b[2]) {
    asm volatile(
        "mma.sync.aligned.m16n8k16.row.col.f32.bf16.bf16.f32 "
        "{%0,%1,%2,%3},{%4,%5,%6,%7},{%8,%9},{%0,%1,%2,%3};"
        : "+f"(d[0]), "+f"(d[1]), "+f"(d[2]), "+f"(d[3])
        : "r"(a[0]), "r"(a[1]), "r"(a[2]), "r"(a[3]), "r"(b[0]), "r"(b[1]));
}

__device__ __forceinline__ uint32_t bf2bits(__nv_bfloat162 h) {
    return *(uint32_t*)&h;
}

__device__ __forceinline__ void cpa16(void* dst, const void* src) {
    uint32_t d = (uint32_t)__cvta_generic_to_shared(dst);
    asm volatile("cp.async.cg.shared.global [%0], [%1], 16;" :: "r"(d), "l"(src));
}

// ---------------- prep: fp32 -> packed bf16x2 hi/lo ----------------
// sel: 0 -> X (g_xh/g_xl), 1..3 -> W q/k/v slot in g_wh/g_wl
__global__ __launch_bounds__(256) void prep_kernel(const float* __restrict__ src, int sel) {
    uint32_t* hi;
    uint32_t* lo;
    if (sel == 0) { hi = g_xh; lo = g_xl; }
    else {
        size_t off = (size_t)(sel - 1) * D_ * (D_ / 2);
        hi = g_wh + off; lo = g_wl + off;
    }
    size_t i = (size_t)blockIdx.x * 256 + threadIdx.x;  // one float4
    float4 a = *(const float4*)&src[i * 4];
    __nv_bfloat162 h01 = __floats2bfloat162_rn(a.x, a.y);
    __nv_bfloat162 h23 = __floats2bfloat162_rn(a.z, a.w);
    float2 f01 = __bfloat1622float2(h01);
    float2 f23 = __bfloat1622float2(h23);
    __nv_bfloat162 l01 = __floats2bfloat162_rn(a.x - f01.x, a.y - f01.y);
    __nv_bfloat162 l23 = __floats2bfloat162_rn(a.z - f23.x, a.w - f23.y);
    *(uint2*)&hi[i * 2] = make_uint2(bf2bits(h01), bf2bits(h23));
    *(uint2*)&lo[i * 2] = make_uint2(bf2bits(l01), bf2bits(l23));
}

// ---------------- projection GEMM (bf16x3, cp.async double-buffered) ----------------
// grid (8, 32, 3); z selects Q/K/V. BM=128, BN=128, BK=32 (16 uint32/row),
// 256 threads, warps 4(m) x 2(n), warp tile 32x64.
// dyn smem: Ah/Al/Bh/Bl, each [2][128][20] uint32 -> 81920 B total.
#define PROJ_SMEM_BYTES (4 * 2 * 128 * 20 * 4)
#define AH_OFF 0
#define AL_OFF 5120
#define BH_OFF 10240
#define BL_OFF 15360

__global__ __launch_bounds__(256, 2) void proj_kernel(const float* __restrict__ bq,
                                                      const float* __restrict__ bk,
                                                      const float* __restrict__ bv) {
    extern __shared__ uint32_t psm[];
    const int z = blockIdx.z;
    const float* bias = (z == 0) ? bq : (z == 1) ? bk : bv;
    float* Y = (z == 0) ? g_q : (z == 1) ? g_k : g_v;
    const uint32_t* xh = g_xh;
    const uint32_t* xl = g_xl;
    const uint32_t* wh = g_wh + (size_t)z * D_ * (D_ / 2);
    const uint32_t* wl = g_wl + (size_t)z * D_ * (D_ / 2);

    const int tid = threadIdx.x;
    const int warp = tid >> 5, lane = tid & 31;
    const int gid = lane >> 2, tig = lane & 3;
    const int wm = warp >> 1, wn = warp & 1;
    const int row0 = blockIdx.y * 128;
    const int col0 = blockIdx.x * 128;

    // chunk mapping for cp.async staging: 512 chunks of 16B per array, 2/thread
    const int ch0 = tid, ch1 = tid + 256;
    const int r0c = ch0 >> 2, c0c = (ch0 & 3) << 2;
    const int r1c = ch1 >> 2, c1c = (ch1 & 3) << 2;

    float acc[2][8][4];
#pragma unroll
    for (int mt = 0; mt < 2; mt++)
#pragma unroll
        for (int nt = 0; nt < 8; nt++)
#pragma unroll
            for (int r = 0; r < 4; r++) acc[mt][nt][r] = 0.f;

    // stage tile kt into buffer buf
    auto stage = [&](int buf, int kt) {
        int kof = kt * 16;
        uint32_t* base = psm + buf * 2560;
        cpa16(&base[AH_OFF + r0c * 20 + c0c], &xh[(size_t)(row0 + r0c) * 512 + kof + c0c]);
        cpa16(&base[AH_OFF + r1c * 20 + c1c], &xh[(size_t)(row0 + r1c) * 512 + kof + c1c]);
        cpa16(&base[AL_OFF + r0c * 20 + c0c], &xl[(size_t)(row0 + r0c) * 512 + kof + c0c]);
        cpa16(&base[AL_OFF + r1c * 20 + c1c], &xl[(size_t)(row0 + r1c) * 512 + kof + c1c]);
        cpa16(&base[BH_OFF + r0c * 20 + c0c], &wh[(size_t)(col0 + r0c) * 512 + kof + c0c]);
        cpa16(&base[BH_OFF + r1c * 20 + c1c], &wh[(size_t)(col0 + r1c) * 512 + kof + c1c]);
        cpa16(&base[BL_OFF + r0c * 20 + c0c], &wl[(size_t)(col0 + r0c) * 512 + kof + c0c]);
        cpa16(&base[BL_OFF + r1c * 20 + c1c], &wl[(size_t)(col0 + r1c) * 512 + kof + c1c]);
        asm volatile("cp.async.commit_group;");
    };

    stage(0, 0);

    for (int kt = 0; kt < 32; kt++) {
        if (kt < 31) {
            stage((kt + 1) & 1, kt + 1);
            asm volatile("cp.async.wait_group 1;");
        } else {
            asm volatile("cp.async.wait_group 0;");
        }
        __syncthreads();

        const uint32_t* base = psm + (kt & 1) * 2560;
#pragma unroll
        for (int kc = 0; kc < 2; kc++) {
            uint32_t ah[2][4], al[2][4];
#pragma unroll
            for (int mt = 0; mt < 2; mt++) {
                int mrow = wm * 32 + mt * 16;
                ah[mt][0] = base[AH_OFF + (mrow + gid) * 20 + kc * 8 + tig];
                ah[mt][1] = base[AH_OFF + (mrow + gid + 8) * 20 + kc * 8 + tig];
                ah[mt][2] = base[AH_OFF + (mrow + gid) * 20 + kc * 8 + tig + 4];
                ah[mt][3] = base[AH_OFF + (mrow + gid + 8) * 20 + kc * 8 + tig + 4];
                al[mt][0] = base[AL_OFF + (mrow + gid) * 20 + kc * 8 + tig];
                al[mt][1] = base[AL_OFF + (mrow + gid + 8) * 20 + kc * 8 + tig];
                al[mt][2] = base[AL_OFF + (mrow + gid) * 20 + kc * 8 + tig + 4];
                al[mt][3] = base[AL_OFF + (mrow + gid + 8) * 20 + kc * 8 + tig + 4];
            }
#pragma unroll
            for (int nt = 0; nt < 8; nt++) {
                int nrow = wn * 64 + nt * 8 + gid;
                uint32_t bh[2], bl[2];
                bh[0] = base[BH_OFF + nrow * 20 + kc * 8 + tig];
                bh[1] = base[BH_OFF + nrow * 20 + kc * 8 + tig + 4];
                bl[0] = base[BL_OFF + nrow * 20 + kc * 8 + tig];
                bl[1] = base[BL_OFF + nrow * 20 + kc * 8 + tig + 4];
#pragma unroll
                for (int mt = 0; mt < 2; mt++) {
                    mma16(acc[mt][nt], ah[mt], bh);
                    mma16(acc[mt][nt], al[mt], bh);
                    mma16(acc[mt][nt], ah[mt], bl);
                }
            }
        }
        __syncthreads();
    }
#pragma unroll
    for (int mt = 0; mt < 2; mt++) {
        int rg = row0 + wm * 32 + mt * 16 + gid;
#pragma unroll
        for (int nt = 0; nt < 8; nt++) {
            int cg = col0 + wn * 64 + nt * 8 + 2 * tig;
            float bx = bias[cg], by = bias[cg + 1];
            *(float2*)&Y[(size_t)rg * D_ + cg] =
                make_float2(acc[mt][nt][0] + bx, acc[mt][nt][1] + by);
            *(float2*)&Y[(size_t)(rg + 8) * D_ + cg] =
                make_float2(acc[mt][nt][2] + bx, acc[mt][nt][3] + by);
        }
    }
}

// ---------------- lm[m,s,t] = sum_r mask1[m,r,s] * mask2[m,r,t] (fp32) ----------------
__global__ __launch_bounds__(256) void lm_kernel(const float* __restrict__ m1,
                                                 const float* __restrict__ m2) {
    __shared__ float As[16][64];
    __shared__ float Bs[16][64];
    const int m = blockIdx.z;
    const int s0 = blockIdx.y * 64, t0 = blockIdx.x * 64;
    const int tid = threadIdx.x;
    const int tx = tid & 15, ty = tid >> 4;
    float acc[4][4];
#pragma unroll
    for (int i = 0; i < 4; i++)
#pragma unroll
        for (int j = 0; j < 4; j++) acc[i][j] = 0.f;

    for (int r0 = 0; r0 < R_; r0 += 16) {
        int rr = tid >> 4, cc = (tid & 15) << 2;
        *(float4*)&As[rr][cc] = *(const float4*)&m1[(size_t)((m * R_ + r0 + rr)) * S_ + s0 + cc];
        *(float4*)&Bs[rr][cc] = *(const float4*)&m2[(size_t)((m * R_ + r0 + rr)) * S_ + t0 + cc];
        __syncthreads();
#pragma unroll
        for (int r = 0; r < 16; r++) {
            float a[4], bb[4];
#pragma unroll
            for (int i = 0; i < 4; i++) a[i] = As[r][ty * 4 + i];
#pragma unroll
            for (int j = 0; j < 4; j++) bb[j] = Bs[r][tx + 16 * j];
#pragma unroll
            for (int i = 0; i < 4; i++)
#pragma unroll
                for (int j = 0; j < 4; j++) acc[i][j] += a[i] * bb[j];
        }
        __syncthreads();
    }
#pragma unroll
    for (int i = 0; i < 4; i++)
#pragma unroll
        for (int j = 0; j < 4; j++)
            g_lm[(size_t)(m * S_ + s0 + ty * 4 + i) * S_ + t0 + tx + 16 * j] = acc[i][j];
}

// ---------------- gathered[m,s,t] = lm[m,s,rb[m,s,t]]  (+ zero ssq) ----------------
__global__ __launch_bounds__(256) void gather_kernel(const int* __restrict__ rb) {
    if (blockIdx.x == 0 && threadIdx.x < B_ * H_) g_ssq[threadIdx.x] = 0.f;
    int i4 = (blockIdx.x * 256 + threadIdx.x) * 4;  // over M*S*S
    int row = i4 >> 10;                             // combined (m*S + s)
    const float* lrow = &g_lm[(size_t)row << 10];
    int4 u = *(const int4*)&rb[i4];
    g_gath[i4 + 0] = lrow[u.x & (S_ - 1)];
    g_gath[i4 + 1] = lrow[u.y & (S_ - 1)];
    g_gath[i4 + 2] = lrow[u.z & (S_ - 1)];
    g_gath[i4 + 3] = lrow[u.w & (S_ - 1)];
}

// ---------------- fused attention (shuffle P re-fragmentation, no P smem) ----------------
#define KSTRIDE 76
#define VSTRIDE 72
#define ATT_SMEM_FLOATS (128 * KSTRIDE + 128 * VSTRIDE)
#define ATT_SMEM_BYTES (ATT_SMEM_FLOATS * 4)

__global__ __launch_bounds__(256, 2) void attn_kernel(float* __restrict__ out) {
    extern __shared__ float sm[];
    float* Ks = sm;                   // 128 x 76 (K tile; Q staged here first)
    float* Vs = sm + 128 * KSTRIDE;   // 128 x 72

    const int tid = threadIdx.x, warp = tid >> 5, lane = tid & 31;
    const int gid = lane >> 2, tig = lane & 3;
    const int bh = blockIdx.y;
    const int b = bh >> 4, h = bh & 15;
    const int midx = h & 3;
    const int s0 = blockIdx.x * 128;
    const int mrow = warp * 16;

    const float* Qg = g_q + (size_t)b * S_ * D_ + h * 64;
    const float* Kg = g_k + (size_t)b * S_ * D_ + h * 64;
    const float* Vg = g_v + (size_t)b * S_ * D_ + h * 64;
    const float* grow = g_gath + (size_t)midx * S_ * S_;

#pragma unroll
    for (int it = 0; it < 8; it++) {
        int i = tid + it * 256;
        int r = i >> 4, c = (i & 15) << 2;
        float4 q4 = *(const float4*)&Qg[(size_t)(s0 + r) * D_ + c];
        *(float4*)&Ks[r * KSTRIDE + c] =
            make_float4(tfbit(q4.x), tfbit(q4.y), tfbit(q4.z), tfbit(q4.w));
    }
    __syncthreads();

    uint32_t qf[8][4];
#pragma unroll
    for (int kc = 0; kc < 8; kc++) {
        qf[kc][0] = __float_as_uint(Ks[(mrow + gid) * KSTRIDE + kc * 8 + tig]);
        qf[kc][1] = __float_as_uint(Ks[(mrow + gid + 8) * KSTRIDE + kc * 8 + tig]);
        qf[kc][2] = __float_as_uint(Ks[(mrow + gid) * KSTRIDE + kc * 8 + tig + 4]);
        qf[kc][3] = __float_as_uint(Ks[(mrow + gid + 8) * KSTRIDE + kc * 8 + tig + 4]);
    }
    __syncthreads();

    float oacc[8][4];
#pragma unroll
    for (int nt = 0; nt < 8; nt++)
#pragma unroll
        for (int r = 0; r < 4; r++) oacc[nt][r] = 0.f;
    float ssq = 0.f;

    const int srcA = (lane & ~3) | (tig >> 1);
    const int srcB = srcA + 2;
    const bool odd = (tig & 1);

    for (int tt = 0; tt < 8; tt++) {
        const int t0 = tt * 128;
#pragma unroll
        for (int it = 0; it < 8; it++) {
            int i = tid + it * 256;
            int r = i >> 4, c = (i & 15) << 2;
            float4 k4 = *(const float4*)&Kg[(size_t)(t0 + r) * D_ + c];
            float4 v4 = *(const float4*)&Vg[(size_t)(t0 + r) * D_ + c];
            *(float4*)&Ks[r * KSTRIDE + c] =
                make_float4(tfbit(k4.x), tfbit(k4.y), tfbit(k4.z), tfbit(k4.w));
            *(float4*)&Vs[r * VSTRIDE + c] =
                make_float4(tfbit(v4.x), tfbit(v4.y), tfbit(v4.z), tfbit(v4.w));
        }
        __syncthreads();

#pragma unroll
        for (int nt = 0; nt < 16; nt++) {
            float p[4] = {0.f, 0.f, 0.f, 0.f};
#pragma unroll
            for (int kc = 0; kc < 8; kc++) {
                uint32_t bf[2];
                bf[0] = __float_as_uint(Ks[(nt * 8 + gid) * KSTRIDE + kc * 8 + tig]);
                bf[1] = __float_as_uint(Ks[(nt * 8 + gid) * KSTRIDE + kc * 8 + tig + 4]);
                mma8(p, qf[kc], bf);
            }
            int srow = s0 + mrow + gid;
            int tcol = t0 + nt * 8 + 2 * tig;
            float2 g0 = *(const float2*)&grow[(size_t)srow * S_ + tcol];
            float2 g1 = *(const float2*)&grow[(size_t)(srow + 8) * S_ + tcol];
            float v0 = p[0] * 0.125f * g0.x;
            float v1 = p[1] * 0.125f * g0.y;
            float v2 = p[2] * 0.125f * g1.x;
            float v3 = p[3] * 0.125f * g1.y;
            ssq += v0 * v0 + v1 * v1 + v2 * v2 + v3 * v3;
            float c0 = tfbit(v0), c1 = tfbit(v1), c2 = tfbit(v2), c3 = tfbit(v3);
            float w00 = __shfl_sync(0xffffffffu, c0, srcA);
            float w01 = __shfl_sync(0xffffffffu, c1, srcA);
            float w10 = __shfl_sync(0xffffffffu, c2, srcA);
            float w11 = __shfl_sync(0xffffffffu, c3, srcA);
            float w20 = __shfl_sync(0xffffffffu, c0, srcB);
            float w21 = __shfl_sync(0xffffffffu, c1, srcB);
            float w30 = __shfl_sync(0xffffffffu, c2, srcB);
            float w31 = __shfl_sync(0xffffffffu, c3, srcB);
            uint32_t af[4];
            af[0] = __float_as_uint(odd ? w01 : w00);
            af[1] = __float_as_uint(odd ? w11 : w10);
            af[2] = __float_as_uint(odd ? w21 : w20);
            af[3] = __float_as_uint(odd ? w31 : w30);
#pragma unroll
            for (int vn = 0; vn < 8; vn++) {
                uint32_t bf[2];
                bf[0] = __float_as_uint(Vs[(nt * 8 + tig) * VSTRIDE + vn * 8 + gid]);
                bf[1] = __float_as_uint(Vs[(nt * 8 + tig + 4) * VSTRIDE + vn * 8 + gid]);
                mma8(oacc[vn], af, bf);
            }
        }
        __syncthreads();
    }

    float* Og = out + (size_t)b * S_ * D_ + h * 64;
#pragma unroll
    for (int nt = 0; nt < 8; nt++) {
        int srow = s0 + mrow + gid;
        int c = nt * 8 + 2 * tig;
        *(float2*)&Og[(size_t)srow * D_ + c] = make_float2(oacc[nt][0], oacc[nt][1]);
        *(float2*)&Og[(size_t)(srow + 8) * D_ + c] = make_float2(oacc[nt][2], oacc[nt][3]);
    }
#pragma unroll
    for (int off = 16; off; off >>= 1) ssq += __shfl_xor_sync(0xffffffffu, ssq, off);
    if (lane == 0) atomicAdd(&g_ssq[bh], ssq);
}

// ---------------- final scale by 1/(||att||_F + eps) ----------------
__global__ __launch_bounds__(256) void scale_kernel(float* __restrict__ out) {
    int i4 = (blockIdx.x * 256 + threadIdx.x) * 4;  // over B*S*D
    int col = i4 & (D_ - 1);
    int h = col >> 6;
    int b = i4 >> 20;  // / (S_*D_)
    float f = 1.f / (sqrtf(g_ssq[b * H_ + h]) + EPS_);
    float4 v = *(float4*)&out[i4];
    v.x *= f; v.y *= f; v.z *= f; v.w *= f;
    *(float4*)&out[i4] = v;
}

// ---------------- launch ----------------
extern "C" void kernel_launch(void* const* d_in, const int* in_sizes, int n_in,
                              void* d_out, int out_size) {
    const float* x = (const float*)d_in[0];
    const float* Wk = (const float*)d_in[1];
    const float* bk = (const float*)d_in[2];
    const float* Wq = (const float*)d_in[3];
    const float* bq = (const float*)d_in[4];
    const float* Wv = (const float*)d_in[5];
    const float* bv = (const float*)d_in[6];
    const float* mask1 = (const float*)d_in[7];
    const float* mask2 = (const float*)d_in[8];
    const int* rb = (const int*)d_in[9];
    float* out = (float*)d_out;

    static bool attr_set = false;
    if (!attr_set) {
        cudaFuncSetAttribute(attn_kernel, cudaFuncAttributeMaxDynamicSharedMemorySize,
                             ATT_SMEM_BYTES);
        cudaFuncSetAttribute(proj_kernel, cudaFuncAttributeMaxDynamicSharedMemorySize,
                             PROJ_SMEM_BYTES);
        attr_set = true;
    }

    // bf16 hi/lo pre-split of X and W (k-packed layout)
    prep_kernel<<<(B_ * S_ * D_) / 1024, 256>>>(x, 0);
    prep_kernel<<<(D_ * D_) / 1024, 256>>>(Wq, 1);
    prep_kernel<<<(D_ * D_) / 1024, 256>>>(Wk, 2);
    prep_kernel<<<(D_ * D_) / 1024, 256>>>(Wv, 3);

    dim3 pgrid(D_ / 128, (B_ * S_) / 128, 3);  // (8, 32, 3)
    proj_kernel<<<pgrid, 256, PROJ_SMEM_BYTES>>>(bq, bk, bv);

    lm_kernel<<<dim3(S_ / 64, S_ / 64, M_), 256>>>(mask1, mask2);
    gather_kernel<<<(M_ * S_ * S_) / 1024, 256>>>(rb);

    attn_kernel<<<dim3(S_ / 128, B_ * H_), 256, ATT_SMEM_BYTES>>>(out);

    scale_kernel<<<(B_ * S_ * D_) / 1024, 256>>>(out);
}

// round 7
// speedup vs baseline: 2.1028x; 1.0825x over previous
#include <cuda_runtime.h>
#include <cuda_bf16.h>
#include <math.h>
#include <stdint.h>

#define B_ 4
#define S_ 1024
#define D_ 1024
#define H_ 16
#define M_ 4
#define R_ 64
#define DH_ 64
#define EPS_ 1e-8f

// ---------------- scratch (static device globals; no allocation) ----------------
__device__ __align__(16) float g_q[B_ * S_ * D_];
__device__ __align__(16) float g_k[B_ * S_ * D_];
__device__ __align__(16) float g_v[B_ * S_ * D_];
__device__ __align__(16) float g_lm[M_ * S_ * S_];
__device__ __align__(16) float g_gath[M_ * S_ * S_];
__device__ __align__(16) float g_ssq[B_ * H_];
// packed bf16x2 (hi/lo split) staging of X and W: [row][k/2]
__device__ __align__(16) uint32_t g_xh[B_ * S_ * (D_ / 2)];
__device__ __align__(16) uint32_t g_xl[B_ * S_ * (D_ / 2)];
__device__ __align__(16) uint32_t g_wh[3 * D_ * (D_ / 2)];
__device__ __align__(16) uint32_t g_wl[3 * D_ * (D_ / 2)];

// ---------------- helpers ----------------
__device__ __forceinline__ uint32_t f2tf(float x) {
    uint32_t u;
    asm("cvt.rna.tf32.f32 %0, %1;" : "=r"(u) : "f"(x));
    return u;
}
__device__ __forceinline__ float tfbit(float x) { return __uint_as_float(f2tf(x)); }

__device__ __forceinline__ void mma8(float d[4], const uint32_t a[4], const uint32_t b[2]) {
    asm volatile(
        "mma.sync.aligned.m16n8k8.row.col.f32.tf32.tf32.f32 "
        "{%0,%1,%2,%3},{%4,%5,%6,%7},{%8,%9},{%0,%1,%2,%3};"
        : "+f"(d[0]), "+f"(d[1]), "+f"(d[2]), "+f"(d[3])
        : "r"(a[0]), "r"(a[1]), "r"(a[2]), "r"(a[3]), "r"(b[0]), "r"(b[1]));
}

__device__ __forceinline__ void mma16(float d[4], const uint32_t a[4], const uint32_t b[2]) {
    asm volatile(
        "mma.sync.aligned.m16n8k16.row.col.f32.bf16.bf16.f32 "
        "{%0,%1,%2,%3},{%4,%5,%6,%7},{%8,%9},{%0,%1,%2,%3};"
        : "+f"(d[0]), "+f"(d[1]), "+f"(d[2]), "+f"(d[3])
        : "r"(a[0]), "r"(a[1]), "r"(a[2]), "r"(a[3]), "r"(b[0]), "r"(b[1]));
}

__device__ __forceinline__ uint32_t bf2bits(__nv_bfloat162 h) {
    return *(uint32_t*)&h;
}

__device__ __forceinline__ void cpa16(void* dst, const void* src) {
    uint32_t d = (uint32_t)__cvta_generic_to_shared(dst);
    asm volatile("cp.async.cg.shared.global [%0], [%1], 16;" :: "r"(d), "l"(src));
}

// ---------------- prep: fp32 -> packed bf16x2 hi/lo ----------------
__global__ __launch_bounds__(256) void prep_x(const float* __restrict__ src) {
    size_t i = (size_t)blockIdx.x * 256 + threadIdx.x;  // one float4
    float4 a = *(const float4*)&src[i * 4];
    __nv_bfloat162 h01 = __floats2bfloat162_rn(a.x, a.y);
    __nv_bfloat162 h23 = __floats2bfloat162_rn(a.z, a.w);
    float2 f01 = __bfloat1622float2(h01);
    float2 f23 = __bfloat1622float2(h23);
    __nv_bfloat162 l01 = __floats2bfloat162_rn(a.x - f01.x, a.y - f01.y);
    __nv_bfloat162 l23 = __floats2bfloat162_rn(a.z - f23.x, a.w - f23.y);
    *(uint2*)&g_xh[i * 2] = make_uint2(bf2bits(h01), bf2bits(h23));
    *(uint2*)&g_xl[i * 2] = make_uint2(bf2bits(l01), bf2bits(l23));
}

__global__ __launch_bounds__(256) void prep_w(const float* __restrict__ q,
                                              const float* __restrict__ k,
                                              const float* __restrict__ v) {
    int z = blockIdx.y;
    const float* src = (z == 0) ? q : (z == 1) ? k : v;
    size_t off = (size_t)z * D_ * (D_ / 2);
    size_t i = (size_t)blockIdx.x * 256 + threadIdx.x;
    float4 a = *(const float4*)&src[i * 4];
    __nv_bfloat162 h01 = __floats2bfloat162_rn(a.x, a.y);
    __nv_bfloat162 h23 = __floats2bfloat162_rn(a.z, a.w);
    float2 f01 = __bfloat1622float2(h01);
    float2 f23 = __bfloat1622float2(h23);
    __nv_bfloat162 l01 = __floats2bfloat162_rn(a.x - f01.x, a.y - f01.y);
    __nv_bfloat162 l23 = __floats2bfloat162_rn(a.z - f23.x, a.w - f23.y);
    *(uint2*)&g_wh[off + i * 2] = make_uint2(bf2bits(h01), bf2bits(h23));
    *(uint2*)&g_wl[off + i * 2] = make_uint2(bf2bits(l01), bf2bits(l23));
}

// ---------------- projection GEMM (bf16x3, cp.async double-buffered) ----------------
// grid (8, 32, 3); z selects Q/K/V. BM=128, BN=128, BK=32 (16 uint32/row),
// 256 threads, warps 4(m) x 2(n), warp tile 32x64.
// Outputs are rounded to tf32 bit patterns (consumed as tf32 by attn).
#define PROJ_SMEM_BYTES (4 * 2 * 128 * 20 * 4)
#define AH_OFF 0
#define AL_OFF 5120
#define BH_OFF 10240
#define BL_OFF 15360

__global__ __launch_bounds__(256, 2) void proj_kernel(const float* __restrict__ bq,
                                                      const float* __restrict__ bk,
                                                      const float* __restrict__ bv) {
    extern __shared__ uint32_t psm[];
    const int z = blockIdx.z;
    const float* bias = (z == 0) ? bq : (z == 1) ? bk : bv;
    float* Y = (z == 0) ? g_q : (z == 1) ? g_k : g_v;
    const uint32_t* xh = g_xh;
    const uint32_t* xl = g_xl;
    const uint32_t* wh = g_wh + (size_t)z * D_ * (D_ / 2);
    const uint32_t* wl = g_wl + (size_t)z * D_ * (D_ / 2);

    const int tid = threadIdx.x;
    const int warp = tid >> 5, lane = tid & 31;
    const int gid = lane >> 2, tig = lane & 3;
    const int wm = warp >> 1, wn = warp & 1;
    const int row0 = blockIdx.y * 128;
    const int col0 = blockIdx.x * 128;

    const int ch0 = tid, ch1 = tid + 256;
    const int r0c = ch0 >> 2, c0c = (ch0 & 3) << 2;
    const int r1c = ch1 >> 2, c1c = (ch1 & 3) << 2;

    float acc[2][8][4];
#pragma unroll
    for (int mt = 0; mt < 2; mt++)
#pragma unroll
        for (int nt = 0; nt < 8; nt++)
#pragma unroll
            for (int r = 0; r < 4; r++) acc[mt][nt][r] = 0.f;

    auto stage = [&](int buf, int kt) {
        int kof = kt * 16;
        uint32_t* base = psm + buf * 2560;
        cpa16(&base[AH_OFF + r0c * 20 + c0c], &xh[(size_t)(row0 + r0c) * 512 + kof + c0c]);
        cpa16(&base[AH_OFF + r1c * 20 + c1c], &xh[(size_t)(row0 + r1c) * 512 + kof + c1c]);
        cpa16(&base[AL_OFF + r0c * 20 + c0c], &xl[(size_t)(row0 + r0c) * 512 + kof + c0c]);
        cpa16(&base[AL_OFF + r1c * 20 + c1c], &xl[(size_t)(row0 + r1c) * 512 + kof + c1c]);
        cpa16(&base[BH_OFF + r0c * 20 + c0c], &wh[(size_t)(col0 + r0c) * 512 + kof + c0c]);
        cpa16(&base[BH_OFF + r1c * 20 + c1c], &wh[(size_t)(col0 + r1c) * 512 + kof + c1c]);
        cpa16(&base[BL_OFF + r0c * 20 + c0c], &wl[(size_t)(col0 + r0c) * 512 + kof + c0c]);
        cpa16(&base[BL_OFF + r1c * 20 + c1c], &wl[(size_t)(col0 + r1c) * 512 + kof + c1c]);
        asm volatile("cp.async.commit_group;");
    };

    stage(0, 0);

    for (int kt = 0; kt < 32; kt++) {
        if (kt < 31) {
            stage((kt + 1) & 1, kt + 1);
            asm volatile("cp.async.wait_group 1;");
        } else {
            asm volatile("cp.async.wait_group 0;");
        }
        __syncthreads();

        const uint32_t* base = psm + (kt & 1) * 2560;
#pragma unroll
        for (int kc = 0; kc < 2; kc++) {
            uint32_t ah[2][4], al[2][4];
#pragma unroll
            for (int mt = 0; mt < 2; mt++) {
                int mrow = wm * 32 + mt * 16;
                ah[mt][0] = base[AH_OFF + (mrow + gid) * 20 + kc * 8 + tig];
                ah[mt][1] = base[AH_OFF + (mrow + gid + 8) * 20 + kc * 8 + tig];
                ah[mt][2] = base[AH_OFF + (mrow + gid) * 20 + kc * 8 + tig + 4];
                ah[mt][3] = base[AH_OFF + (mrow + gid + 8) * 20 + kc * 8 + tig + 4];
                al[mt][0] = base[AL_OFF + (mrow + gid) * 20 + kc * 8 + tig];
                al[mt][1] = base[AL_OFF + (mrow + gid + 8) * 20 + kc * 8 + tig];
                al[mt][2] = base[AL_OFF + (mrow + gid) * 20 + kc * 8 + tig + 4];
                al[mt][3] = base[AL_OFF + (mrow + gid + 8) * 20 + kc * 8 + tig + 4];
            }
#pragma unroll
            for (int nt = 0; nt < 8; nt++) {
                int nrow = wn * 64 + nt * 8 + gid;
                uint32_t bh[2], bl[2];
                bh[0] = base[BH_OFF + nrow * 20 + kc * 8 + tig];
                bh[1] = base[BH_OFF + nrow * 20 + kc * 8 + tig + 4];
                bl[0] = base[BL_OFF + nrow * 20 + kc * 8 + tig];
                bl[1] = base[BL_OFF + nrow * 20 + kc * 8 + tig + 4];
#pragma unroll
                for (int mt = 0; mt < 2; mt++) {
                    mma16(acc[mt][nt], ah[mt], bh);
                    mma16(acc[mt][nt], al[mt], bh);
                    mma16(acc[mt][nt], ah[mt], bl);
                }
            }
        }
        __syncthreads();
    }
    // epilogue: bias, then round to tf32 bit pattern (attn consumes as tf32)
#pragma unroll
    for (int mt = 0; mt < 2; mt++) {
        int rg = row0 + wm * 32 + mt * 16 + gid;
#pragma unroll
        for (int nt = 0; nt < 8; nt++) {
            int cg = col0 + wn * 64 + nt * 8 + 2 * tig;
            float bx = bias[cg], by = bias[cg + 1];
            *(float2*)&Y[(size_t)rg * D_ + cg] =
                make_float2(tfbit(acc[mt][nt][0] + bx), tfbit(acc[mt][nt][1] + by));
            *(float2*)&Y[(size_t)(rg + 8) * D_ + cg] =
                make_float2(tfbit(acc[mt][nt][2] + bx), tfbit(acc[mt][nt][3] + by));
        }
    }
}

// ---------------- lm[m,s,t] = sum_r mask1[m,r,s] * mask2[m,r,t] (fp32) ----------------
__global__ __launch_bounds__(256) void lm_kernel(const float* __restrict__ m1,
                                                 const float* __restrict__ m2) {
    __shared__ float As[16][64];
    __shared__ float Bs[16][64];
    const int m = blockIdx.z;
    const int s0 = blockIdx.y * 64, t0 = blockIdx.x * 64;
    const int tid = threadIdx.x;
    const int tx = tid & 15, ty = tid >> 4;
    float acc[4][4];
#pragma unroll
    for (int i = 0; i < 4; i++)
#pragma unroll
        for (int j = 0; j < 4; j++) acc[i][j] = 0.f;

    for (int r0 = 0; r0 < R_; r0 += 16) {
        int rr = tid >> 4, cc = (tid & 15) << 2;
        *(float4*)&As[rr][cc] = *(const float4*)&m1[(size_t)((m * R_ + r0 + rr)) * S_ + s0 + cc];
        *(float4*)&Bs[rr][cc] = *(const float4*)&m2[(size_t)((m * R_ + r0 + rr)) * S_ + t0 + cc];
        __syncthreads();
#pragma unroll
        for (int r = 0; r < 16; r++) {
            float a[4], bb[4];
#pragma unroll
            for (int i = 0; i < 4; i++) a[i] = As[r][ty * 4 + i];
#pragma unroll
            for (int j = 0; j < 4; j++) bb[j] = Bs[r][tx + 16 * j];
#pragma unroll
            for (int i = 0; i < 4; i++)
#pragma unroll
                for (int j = 0; j < 4; j++) acc[i][j] += a[i] * bb[j];
        }
        __syncthreads();
    }
#pragma unroll
    for (int i = 0; i < 4; i++)
#pragma unroll
        for (int j = 0; j < 4; j++)
            g_lm[(size_t)(m * S_ + s0 + ty * 4 + i) * S_ + t0 + tx + 16 * j] = acc[i][j];
}

// ---------------- gathered[m,s,t] = lm[m,s,rb[m,s,t]]  (+ zero ssq) ----------------
__global__ __launch_bounds__(256) void gather_kernel(const int* __restrict__ rb) {
    if (blockIdx.x == 0 && threadIdx.x < B_ * H_) g_ssq[threadIdx.x] = 0.f;
    int i4 = (blockIdx.x * 256 + threadIdx.x) * 4;  // over M*S*S
    int row = i4 >> 10;                             // combined (m*S + s)
    const float* lrow = &g_lm[(size_t)row << 10];
    int4 u = *(const int4*)&rb[i4];
    g_gath[i4 + 0] = lrow[u.x & (S_ - 1)];
    g_gath[i4 + 1] = lrow[u.y & (S_ - 1)];
    g_gath[i4 + 2] = lrow[u.z & (S_ - 1)];
    g_gath[i4 + 3] = lrow[u.w & (S_ - 1)];
}

// ---------------- fused attention (cp.async double-buffered 64-row t-tiles) ----------------
// grid (S/128, B*H), 256 thr (8 warps, warp tile m=16). q/k/v already tf32-rounded.
// smem per buffer: K 64x76, V 64x72 floats; 2 buffers.
#define KSTRIDE 76
#define VSTRIDE 72
#define ATT_BUF_FLOATS (64 * KSTRIDE + 64 * VSTRIDE)
#define ATT_SMEM_BYTES (2 * ATT_BUF_FLOATS * 4)

__global__ __launch_bounds__(256, 2) void attn_kernel(float* __restrict__ out) {
    extern __shared__ float sm[];

    const int tid = threadIdx.x, warp = tid >> 5, lane = tid & 31;
    const int gid = lane >> 2, tig = lane & 3;
    const int bh = blockIdx.y;
    const int b = bh >> 4, h = bh & 15;
    const int midx = h & 3;
    const int s0 = blockIdx.x * 128;
    const int mrow = warp * 16;

    const float* Qg = g_q + (size_t)b * S_ * D_ + h * 64;
    const float* Kg = g_k + (size_t)b * S_ * D_ + h * 64;
    const float* Vg = g_v + (size_t)b * S_ * D_ + h * 64;
    const float* grow = g_gath + (size_t)midx * S_ * S_;

    // Q fragments direct from gmem (values are tf32 bit patterns already)
    uint32_t qf[8][4];
    {
        const float* Qr0 = &Qg[(size_t)(s0 + mrow + gid) * D_];
        const float* Qr1 = &Qg[(size_t)(s0 + mrow + gid + 8) * D_];
#pragma unroll
        for (int kc = 0; kc < 8; kc++) {
            qf[kc][0] = __float_as_uint(Qr0[kc * 8 + tig]);
            qf[kc][1] = __float_as_uint(Qr1[kc * 8 + tig]);
            qf[kc][2] = __float_as_uint(Qr0[kc * 8 + tig + 4]);
            qf[kc][3] = __float_as_uint(Qr1[kc * 8 + tig + 4]);
        }
    }

    float oacc[8][4];
#pragma unroll
    for (int nt = 0; nt < 8; nt++)
#pragma unroll
        for (int r = 0; r < 4; r++) oacc[nt][r] = 0.f;
    float ssq = 0.f;

    const int srcA = (lane & ~3) | (tig >> 1);
    const int srcB = srcA + 2;
    const bool odd = (tig & 1);

    // stage 64-row K/V tile tt into buffer tt&1 (16B cp.async chunks)
    auto stage = [&](int tt) {
        const int t0 = tt * 64;
        float* base = sm + (tt & 1) * ATT_BUF_FLOATS;
#pragma unroll
        for (int t = 0; t < 4; t++) {
            int id = tid + t * 256;
            int r = id >> 4, c = (id & 15) << 2;
            cpa16(&base[r * KSTRIDE + c], &Kg[(size_t)(t0 + r) * D_ + c]);
            cpa16(&base[64 * KSTRIDE + r * VSTRIDE + c], &Vg[(size_t)(t0 + r) * D_ + c]);
        }
        asm volatile("cp.async.commit_group;");
    };

    stage(0);

    for (int tt = 0; tt < 16; tt++) {
        if (tt < 15) {
            stage(tt + 1);
            asm volatile("cp.async.wait_group 1;");
        } else {
            asm volatile("cp.async.wait_group 0;");
        }
        __syncthreads();

        const float* Ks = sm + (tt & 1) * ATT_BUF_FLOATS;
        const float* Vs = Ks + 64 * KSTRIDE;
        const int t0 = tt * 64;

#pragma unroll
        for (int nt = 0; nt < 8; nt++) {
            float p[4] = {0.f, 0.f, 0.f, 0.f};
#pragma unroll
            for (int kc = 0; kc < 8; kc++) {
                uint32_t bf[2];
                bf[0] = __float_as_uint(Ks[(nt * 8 + gid) * KSTRIDE + kc * 8 + tig]);
                bf[1] = __float_as_uint(Ks[(nt * 8 + gid) * KSTRIDE + kc * 8 + tig + 4]);
                mma8(p, qf[kc], bf);
            }
            int srow = s0 + mrow + gid;
            int tcol = t0 + nt * 8 + 2 * tig;
            float2 g0 = *(const float2*)&grow[(size_t)srow * S_ + tcol];
            float2 g1 = *(const float2*)&grow[(size_t)(srow + 8) * S_ + tcol];
            float v0 = p[0] * 0.125f * g0.x;
            float v1 = p[1] * 0.125f * g0.y;
            float v2 = p[2] * 0.125f * g1.x;
            float v3 = p[3] * 0.125f * g1.y;
            ssq += v0 * v0 + v1 * v1 + v2 * v2 + v3 * v3;
            float c0 = tfbit(v0), c1 = tfbit(v1), c2 = tfbit(v2), c3 = tfbit(v3);
            float w00 = __shfl_sync(0xffffffffu, c0, srcA);
            float w01 = __shfl_sync(0xffffffffu, c1, srcA);
            float w10 = __shfl_sync(0xffffffffu, c2, srcA);
            float w11 = __shfl_sync(0xffffffffu, c3, srcA);
            float w20 = __shfl_sync(0xffffffffu, c0, srcB);
            float w21 = __shfl_sync(0xffffffffu, c1, srcB);
            float w30 = __shfl_sync(0xffffffffu, c2, srcB);
            float w31 = __shfl_sync(0xffffffffu, c3, srcB);
            uint32_t af[4];
            af[0] = __float_as_uint(odd ? w01 : w00);
            af[1] = __float_as_uint(odd ? w11 : w10);
            af[2] = __float_as_uint(odd ? w21 : w20);
            af[3] = __float_as_uint(odd ? w31 : w30);
#pragma unroll
            for (int vn = 0; vn < 8; vn++) {
                uint32_t bf[2];
                bf[0] = __float_as_uint(Vs[(nt * 8 + tig) * VSTRIDE + vn * 8 + gid]);
                bf[1] = __float_as_uint(Vs[(nt * 8 + tig + 4) * VSTRIDE + vn * 8 + gid]);
                mma8(oacc[vn], af, bf);
            }
        }
        __syncthreads();
    }

    float* Og = out + (size_t)b * S_ * D_ + h * 64;
#pragma unroll
    for (int nt = 0; nt < 8; nt++) {
        int srow = s0 + mrow + gid;
        int c = nt * 8 + 2 * tig;
        *(float2*)&Og[(size_t)srow * D_ + c] = make_float2(oacc[nt][0], oacc[nt][1]);
        *(float2*)&Og[(size_t)(srow + 8) * D_ + c] = make_float2(oacc[nt][2], oacc[nt][3]);
    }
#pragma unroll
    for (int off = 16; off; off >>= 1) ssq += __shfl_xor_sync(0xffffffffu, ssq, off);
    if (lane == 0) atomicAdd(&g_ssq[bh], ssq);
}

// ---------------- final scale by 1/(||att||_F + eps) ----------------
__global__ __launch_bounds__(256) void scale_kernel(float* __restrict__ out) {
    int i4 = (blockIdx.x * 256 + threadIdx.x) * 4;  // over B*S*D
    int col = i4 & (D_ - 1);
    int h = col >> 6;
    int b = i4 >> 20;  // / (S_*D_)
    float f = 1.f / (sqrtf(g_ssq[b * H_ + h]) + EPS_);
    float4 v = *(float4*)&out[i4];
    v.x *= f; v.y *= f; v.z *= f; v.w *= f;
    *(float4*)&out[i4] = v;
}

// ---------------- launch ----------------
extern "C" void kernel_launch(void* const* d_in, const int* in_sizes, int n_in,
                              void* d_out, int out_size) {
    const float* x = (const float*)d_in[0];
    const float* Wk = (const float*)d_in[1];
    const float* bk = (const float*)d_in[2];
    const float* Wq = (const float*)d_in[3];
    const float* bq = (const float*)d_in[4];
    const float* Wv = (const float*)d_in[5];
    const float* bv = (const float*)d_in[6];
    const float* mask1 = (const float*)d_in[7];
    const float* mask2 = (const float*)d_in[8];
    const int* rb = (const int*)d_in[9];
    float* out = (float*)d_out;

    static bool attr_set = false;
    if (!attr_set) {
        cudaFuncSetAttribute(attn_kernel, cudaFuncAttributeMaxDynamicSharedMemorySize,
                             ATT_SMEM_BYTES);
        cudaFuncSetAttribute(proj_kernel, cudaFuncAttributeMaxDynamicSharedMemorySize,
                             PROJ_SMEM_BYTES);
        attr_set = true;
    }

    // bf16 hi/lo pre-split of X and W (k-packed layout)
    prep_x<<<(B_ * S_ * D_) / 1024, 256>>>(x);
    prep_w<<<dim3((D_ * D_) / 1024, 3), 256>>>(Wq, Wk, Wv);

    dim3 pgrid(D_ / 128, (B_ * S_) / 128, 3);  // (8, 32, 3)
    proj_kernel<<<pgrid, 256, PROJ_SMEM_BYTES>>>(bq, bk, bv);

    lm_kernel<<<dim3(S_ / 64, S_ / 64, M_), 256>>>(mask1, mask2);
    gather_kernel<<<(M_ * S_ * S_) / 1024, 256>>>(rb);

    attn_kernel<<<dim3(S_ / 128, B_ * H_), 256, ATT_SMEM_BYTES>>>(out);

    scale_kernel<<<(B_ * S_ * D_) / 1024, 256>>>(out);
}